// round 10
// baseline (speedup 1.0000x reference)
#include <cuda_runtime.h>
#include <cuda_bf16.h>
#include <math.h>
#include <stdint.h>

#define NLAYER 5
#define BATCH 4
#define SEQ 1024
#define DIM 768
#define NH 12
#define HD 64
#define TD (3*DIM)
#define FD (4*DIM)
#define MTOK (BATCH*SEQ)   /* 4096 */

typedef __nv_bfloat16 bf16;

// ---------------- scratch (no allocations allowed) ----------------
__device__ float g_h[MTOK*DIM];
__device__ float g_a[MTOK*DIM];
__device__ float g_n[MTOK*DIM];
__device__ float g_m[MTOK*DIM];
__device__ __align__(128) bf16 g_hh[MTOK*DIM],  g_hl[MTOK*DIM];
__device__ __align__(128) bf16 g_qkvh[MTOK*TD], g_qkvl[MTOK*TD];
__device__ __align__(128) bf16 g_ath[MTOK*DIM], g_atl[MTOK*DIM];
__device__ __align__(128) bf16 g_nh[MTOK*DIM],  g_nl[MTOK*DIM];
__device__ __align__(128) bf16 g_fch[MTOK*FD],  g_fcl[MTOK*FD];
// all-layer transposed weights (hi/lo)
__device__ __align__(128) bf16 g_wqh[NLAYER*TD*DIM],  g_wql[NLAYER*TD*DIM];
__device__ __align__(128) bf16 g_wph[NLAYER*DIM*DIM], g_wpl[NLAYER*DIM*DIM];
__device__ __align__(128) bf16 g_wfh[NLAYER*FD*DIM],  g_wfl[NLAYER*FD*DIM];
__device__ __align__(128) bf16 g_wmh[NLAYER*DIM*FD],  g_wml[NLAYER*DIM*FD];

// ---------------- helpers ----------------
__device__ __forceinline__ uint32_t smem_u32(const void* p) {
    uint32_t a;
    asm("{ .reg .u64 t; cvta.to.shared.u64 t, %1; cvt.u32.u64 %0, t; }" : "=r"(a) : "l"(p));
    return a;
}

#define LDSM4(r0, r1, r2, r3, a) \
    asm volatile("ldmatrix.sync.aligned.m8n8.x4.shared.b16 {%0,%1,%2,%3}, [%4];" \
                 : "=r"(r0), "=r"(r1), "=r"(r2), "=r"(r3) : "r"(a))
#define LDSM4T(r0, r1, r2, r3, a) \
    asm volatile("ldmatrix.sync.aligned.m8n8.x4.trans.shared.b16 {%0,%1,%2,%3}, [%4];" \
                 : "=r"(r0), "=r"(r1), "=r"(r2), "=r"(r3) : "r"(a))

#define MMA16816(d, a, b) \
    asm volatile("mma.sync.aligned.m16n8k16.row.col.f32.bf16.bf16.f32 " \
                 "{%0,%1,%2,%3},{%4,%5,%6,%7},{%8,%9},{%0,%1,%2,%3};" \
                 : "+f"((d)[0]), "+f"((d)[1]), "+f"((d)[2]), "+f"((d)[3]) \
                 : "r"((a)[0]), "r"((a)[1]), "r"((a)[2]), "r"((a)[3]), \
                   "r"((b)[0]), "r"((b)[1]))

#define CP_ASYNC16(dst, src) \
    asm volatile("cp.async.cg.shared.global [%0], [%1], 16;" :: "r"(dst), "l"(src) : "memory")
#define CP_COMMIT() asm volatile("cp.async.commit_group;" ::: "memory")
#define CP_WAIT0()  asm volatile("cp.async.wait_group 0;" ::: "memory")
#define CP_WAIT1()  asm volatile("cp.async.wait_group 1;" ::: "memory")
#define CP_WAIT2()  asm volatile("cp.async.wait_group 2;" ::: "memory")

__device__ __forceinline__ uint32_t pk(bf16 a, bf16 b) {
    __nv_bfloat162 v(a, b);
    return *(uint32_t*)&v;
}
__device__ __forceinline__ void split2(float x0, float x1, uint32_t& hi, uint32_t& lo) {
    bf16 h0 = __float2bfloat16_rn(x0);
    bf16 h1 = __float2bfloat16_rn(x1);
    bf16 l0 = __float2bfloat16_rn(x0 - __bfloat162float(h0));
    bf16 l1 = __float2bfloat16_rn(x1 - __bfloat162float(h1));
    hi = pk(h0, h1); lo = pk(l0, l1);
}

__device__ __forceinline__ float gelu_f(float x) {
    float x3 = x * x * x;
    return 0.5f * x * (1.0f + tanhf(0.7978845608028654f * (x + 0.044715f * x3)));
}

// ---------------- embedding (fp32 + split bf16) ----------------
__global__ void embed_kernel(const int* __restrict__ ids,
                             const float* __restrict__ tok_emb,
                             const float* __restrict__ pos_emb,
                             float* __restrict__ out,
                             bf16* __restrict__ oh, bf16* __restrict__ ol) {
    int idx = blockIdx.x * blockDim.x + threadIdx.x;
    if (idx >= MTOK * DIM / 4) return;
    int d4  = idx % (DIM / 4);
    int bs  = idx / (DIM / 4);
    int s   = bs % SEQ;
    int tok = ids[bs];
    float4 t = *(const float4*)&tok_emb[(size_t)tok * DIM + d4 * 4];
    float4 p = *(const float4*)&pos_emb[(size_t)s   * DIM + d4 * 4];
    float4 o = make_float4(t.x + p.x, t.y + p.y, t.z + p.z, t.w + p.w);
    size_t off = (size_t)bs * DIM + d4 * 4;
    *(float4*)&out[off] = o;
    uint32_t h01, l01, h23, l23;
    split2(o.x, o.y, h01, l01);
    split2(o.z, o.w, h23, l23);
    *(uint32_t*)&oh[off]     = h01; *(uint32_t*)&oh[off + 2] = h23;
    *(uint32_t*)&ol[off]     = l01; *(uint32_t*)&ol[off + 2] = l23;
}

// ---------------- batched transpose + fp32 -> bf16 hi/lo split ----------------
__global__ __launch_bounds__(256)
void transpose_conv(const float* __restrict__ W,
                    bf16* __restrict__ Th, bf16* __restrict__ Tl,
                    int K, int N) {
    __shared__ float t[32][33];
    const size_t lw = (size_t)blockIdx.z * K * N;
    const float* Wl = W + lw;
    bf16* Thl = Th + lw;
    bf16* Tll = Tl + lw;
    int n0 = blockIdx.x * 32, k0 = blockIdx.y * 32;
    int tx = threadIdx.x & 31, ty = threadIdx.x >> 5;
    #pragma unroll
    for (int i = 0; i < 4; i++)
        t[ty + i * 8][tx] = Wl[(size_t)(k0 + ty + i * 8) * N + n0 + tx];
    __syncthreads();
    #pragma unroll
    for (int i = 0; i < 4; i++) {
        float v = t[tx][ty + i * 8];
        bf16 h = __float2bfloat16_rn(v);
        bf16 l = __float2bfloat16_rn(v - __bfloat162float(h));
        size_t off = (size_t)(n0 + ty + i * 8) * K + k0 + tx;
        Thl[off] = h;
        Tll[off] = l;
    }
}

// ============ NB=128 GEMM: 4-stage, K-chunk 16, wait_group 2 ============
// stage layout: A_hi[128x48B] | A_lo | B_hi | B_lo ; stage = 24576 B, 4 stages.
#define STG16  24576
#define OAL16  6144
#define OBH16  12288
#define OBL16  18432
#define GEMM_SMEM128 (4 * STG16)

__device__ __forceinline__ void load_stage16(uint32_t dst,
        const bf16* A0, const bf16* A1, const bf16* B0, const bf16* B1,
        int K, int kcol, int tid) {
    int r = tid >> 1, c = tid & 1;
    size_t so = (size_t)r * K + kcol + c * 8;
    uint32_t dof = (uint32_t)(r * 48 + c * 16);
    CP_ASYNC16(dst + dof,           A0 + so);
    CP_ASYNC16(dst + OAL16 + dof,   A1 + so);
    CP_ASYNC16(dst + OBH16 + dof,   B0 + so);
    CP_ASYNC16(dst + OBL16 + dof,   B1 + so);
}

template<int EPI>
__global__ __launch_bounds__(256, 2)
void gemm_p128(const bf16* __restrict__ Ah, const bf16* __restrict__ Al,
               const bf16* __restrict__ Bh, const bf16* __restrict__ Bl,
               const float* __restrict__ bias, float* __restrict__ Cf,
               bf16* __restrict__ Ch, bf16* __restrict__ Cl,
               int M, int N, int K) {
    extern __shared__ char dsm[];
    uint32_t sb = smem_u32(dsm);
    const int tid = threadIdx.x;
    const int lane = tid & 31, wid = tid >> 5;
    const int warp_m = wid & 1;
    const int warp_n = wid >> 1;
    const uint32_t lm_off = (uint32_t)(((lane & 7) + ((lane >> 3) & 1) * 8) * 48
                                       + ((lane >> 4) & 1) * 16);
    const int nk = K >> 4;
    const int mtiles = M >> 7;
    const int tiles = mtiles * (N >> 7);

    for (int t = blockIdx.x; t < tiles; t += gridDim.x) {
        const int m0 = (t % mtiles) << 7;
        const int n0 = (t / mtiles) << 7;
        const bf16* tA0 = Ah + (size_t)m0 * K;
        const bf16* tA1 = Al + (size_t)m0 * K;
        const bf16* tB0 = Bh + (size_t)n0 * K;
        const bf16* tB1 = Bl + (size_t)n0 * K;

        // prologue: stages 0..2 (nk = 48 or 192, always >= 3)
        #pragma unroll
        for (int s = 0; s < 3; s++) {
            load_stage16(sb + s * STG16, tA0, tA1, tB0, tB1, K, s * 16, tid);
            CP_COMMIT();
        }

        float acc[4][4][4] = {};
        for (int kc = 0; kc < nk; kc++) {
            const int rem = nk - 1 - kc;
            if (rem >= 2)      CP_WAIT2();
            else if (rem == 1) CP_WAIT1();
            else               CP_WAIT0();
            __syncthreads();
            if (kc + 3 < nk) {
                load_stage16(sb + ((kc + 3) & 3) * STG16, tA0, tA1, tB0, tB1,
                             K, (kc + 3) * 16, tid);
                CP_COMMIT();
            }
            const uint32_t sA = sb + (uint32_t)((kc & 3) * STG16);

            uint32_t ah[4][4], al[4][4], bh[4][2], bl[4][2];
            // pass 1: Ah x Bh
            #pragma unroll
            for (int mt = 0; mt < 4; mt++) {
                uint32_t ad = sA + (uint32_t)((warp_m * 64 + mt * 16) * 48) + lm_off;
                LDSM4(ah[mt][0], ah[mt][1], ah[mt][2], ah[mt][3], ad);
            }
            #pragma unroll
            for (int ntp = 0; ntp < 2; ntp++) {
                uint32_t bd = sA + OBH16 + (uint32_t)((warp_n * 32 + ntp * 16) * 48) + lm_off;
                uint32_t r0, r1, r2, r3;
                LDSM4(r0, r1, r2, r3, bd);
                bh[2 * ntp][0] = r0; bh[2 * ntp][1] = r2;
                bh[2 * ntp + 1][0] = r1; bh[2 * ntp + 1][1] = r3;
            }
            #pragma unroll
            for (int mt = 0; mt < 4; mt++)
                #pragma unroll
                for (int nt = 0; nt < 4; nt++)
                    MMA16816(acc[mt][nt], ah[mt], bh[nt]);
            // pass 2: Ah x Bl
            #pragma unroll
            for (int ntp = 0; ntp < 2; ntp++) {
                uint32_t bd = sA + OBL16 + (uint32_t)((warp_n * 32 + ntp * 16) * 48) + lm_off;
                uint32_t r0, r1, r2, r3;
                LDSM4(r0, r1, r2, r3, bd);
                bl[2 * ntp][0] = r0; bl[2 * ntp][1] = r2;
                bl[2 * ntp + 1][0] = r1; bl[2 * ntp + 1][1] = r3;
            }
            #pragma unroll
            for (int mt = 0; mt < 4; mt++)
                #pragma unroll
                for (int nt = 0; nt < 4; nt++)
                    MMA16816(acc[mt][nt], ah[mt], bl[nt]);
            // pass 3: Al x Bh
            #pragma unroll
            for (int mt = 0; mt < 4; mt++) {
                uint32_t ad = sA + OAL16 + (uint32_t)((warp_m * 64 + mt * 16) * 48) + lm_off;
                LDSM4(al[mt][0], al[mt][1], al[mt][2], al[mt][3], ad);
            }
            #pragma unroll
            for (int mt = 0; mt < 4; mt++)
                #pragma unroll
                for (int nt = 0; nt < 4; nt++)
                    MMA16816(acc[mt][nt], al[mt], bh[nt]);
        }

        // epilogue
        #pragma unroll
        for (int mt = 0; mt < 4; mt++) {
            int r = m0 + warp_m * 64 + mt * 16 + (lane >> 2);
            #pragma unroll
            for (int nt = 0; nt < 4; nt++) {
                int ccol = n0 + warp_n * 32 + nt * 8 + (lane & 3) * 2;
                float2 bb = *(const float2*)&bias[ccol];
                float x0 = acc[mt][nt][0] + bb.x;
                float x1 = acc[mt][nt][1] + bb.y;
                float x2 = acc[mt][nt][2] + bb.x;
                float x3 = acc[mt][nt][3] + bb.y;
                if (EPI == 2) { x0 = gelu_f(x0); x1 = gelu_f(x1); x2 = gelu_f(x2); x3 = gelu_f(x3); }
                uint32_t hi, lo;
                split2(x0, x1, hi, lo);
                *(uint32_t*)&Ch[(size_t)r * N + ccol] = hi;
                *(uint32_t*)&Cl[(size_t)r * N + ccol] = lo;
                split2(x2, x3, hi, lo);
                *(uint32_t*)&Ch[(size_t)(r + 8) * N + ccol] = hi;
                *(uint32_t*)&Cl[(size_t)(r + 8) * N + ccol] = lo;
            }
        }
        (void)Cf;
    }
}

// ============ NB=64 GEMM: unchanged R6 (double-buffer, K-chunk 32) ============
__device__ __forceinline__ void load_stage64(uint32_t dst,
        const bf16* A0, const bf16* A1, const bf16* B0, const bf16* B1,
        int K, int kcol, int tid) {
    #pragma unroll
    for (int i = 0; i < 8; i++) {
        const int sel = i >> 2;
        int g = tid + (i & 3) * 128;
        int r = g >> 2, c = g & 3;
        const bf16* src = (sel ? A1 : A0) + (size_t)r * K + kcol + c * 8;
        CP_ASYNC16(dst + sel * 10240 + r * 80 + c * 16, src);
    }
    #pragma unroll
    for (int i = 0; i < 4; i++) {
        const int sel = i >> 1;
        int g = tid + (i & 1) * 128;
        int r = g >> 2, c = g & 3;
        const bf16* src = (sel ? B1 : B0) + (size_t)r * K + kcol + c * 8;
        CP_ASYNC16(dst + 20480 + sel * (64 * 80) + r * 80 + c * 16, src);
    }
}

__global__ __launch_bounds__(128, 3)
void gemm_p64(const bf16* __restrict__ Ah, const bf16* __restrict__ Al,
              const bf16* __restrict__ Bh, const bf16* __restrict__ Bl,
              const float* __restrict__ bias, float* __restrict__ Cf,
              int M, int N, int K) {
    constexpr uint32_t OAL = 10240;
    constexpr uint32_t OBH = 20480;
    constexpr uint32_t OBL = 20480 + 64 * 80;
    constexpr uint32_t BUF = 20480 + 2 * 64 * 80;
    extern __shared__ char dsm[];
    uint32_t sb = smem_u32(dsm);
    const int tid = threadIdx.x;
    const int lane = tid & 31, wid = tid >> 5;
    const int warp_m = wid & 1;
    const int warp_n = wid >> 1;
    const uint32_t lm_off = (uint32_t)(((lane & 7) + ((lane >> 3) & 1) * 8) * 80
                                       + ((lane >> 4) & 1) * 16);
    const int nk = K >> 5;
    const int mtiles = M >> 7;
    const int tiles = mtiles * (N >> 6);

    for (int t = blockIdx.x; t < tiles; t += gridDim.x) {
        const int m0 = (t % mtiles) << 7;
        const int n0 = (t / mtiles) << 6;
        const bf16* tA0 = Ah + (size_t)m0 * K;
        const bf16* tA1 = Al + (size_t)m0 * K;
        const bf16* tB0 = Bh + (size_t)n0 * K;
        const bf16* tB1 = Bl + (size_t)n0 * K;

        load_stage64(sb, tA0, tA1, tB0, tB1, K, 0, tid);
        CP_COMMIT();

        float acc[4][4][4] = {};
        for (int kc = 0; kc < nk; kc++) {
            CP_WAIT0();
            __syncthreads();
            if (kc + 1 < nk) {
                load_stage64(sb + ((kc + 1) & 1) * BUF, tA0, tA1, tB0, tB1,
                             K, (kc + 1) * 32, tid);
                CP_COMMIT();
            }
            const uint32_t sA = sb + (uint32_t)((kc & 1) * BUF);
            #pragma unroll
            for (int ks = 0; ks < 2; ks++) {
                uint32_t ah[4][4], al[4][4], bh[4][2], bl[4][2];
                #pragma unroll
                for (int mt = 0; mt < 4; mt++) {
                    uint32_t ad = sA + (uint32_t)((warp_m * 64 + mt * 16) * 80 + ks * 32) + lm_off;
                    LDSM4(ah[mt][0], ah[mt][1], ah[mt][2], ah[mt][3], ad);
                }
                #pragma unroll
                for (int ntp = 0; ntp < 2; ntp++) {
                    uint32_t bd = sA + OBH +
                                  (uint32_t)((warp_n * 32 + ntp * 16) * 80 + ks * 32) + lm_off;
                    uint32_t r0, r1, r2, r3;
                    LDSM4(r0, r1, r2, r3, bd);
                    bh[2 * ntp][0] = r0; bh[2 * ntp][1] = r2;
                    bh[2 * ntp + 1][0] = r1; bh[2 * ntp + 1][1] = r3;
                }
                #pragma unroll
                for (int mt = 0; mt < 4; mt++)
                    #pragma unroll
                    for (int nt = 0; nt < 4; nt++)
                        MMA16816(acc[mt][nt], ah[mt], bh[nt]);
                #pragma unroll
                for (int ntp = 0; ntp < 2; ntp++) {
                    uint32_t bd = sA + OBL +
                                  (uint32_t)((warp_n * 32 + ntp * 16) * 80 + ks * 32) + lm_off;
                    uint32_t r0, r1, r2, r3;
                    LDSM4(r0, r1, r2, r3, bd);
                    bl[2 * ntp][0] = r0; bl[2 * ntp][1] = r2;
                    bl[2 * ntp + 1][0] = r1; bl[2 * ntp + 1][1] = r3;
                }
                #pragma unroll
                for (int mt = 0; mt < 4; mt++)
                    #pragma unroll
                    for (int nt = 0; nt < 4; nt++)
                        MMA16816(acc[mt][nt], ah[mt], bl[nt]);
                #pragma unroll
                for (int mt = 0; mt < 4; mt++) {
                    uint32_t ad = sA + OAL +
                                  (uint32_t)((warp_m * 64 + mt * 16) * 80 + ks * 32) + lm_off;
                    LDSM4(al[mt][0], al[mt][1], al[mt][2], al[mt][3], ad);
                }
                #pragma unroll
                for (int mt = 0; mt < 4; mt++)
                    #pragma unroll
                    for (int nt = 0; nt < 4; nt++)
                        MMA16816(acc[mt][nt], al[mt], bh[nt]);
            }
        }

        #pragma unroll
        for (int mt = 0; mt < 4; mt++) {
            int r = m0 + warp_m * 64 + mt * 16 + (lane >> 2);
            #pragma unroll
            for (int nt = 0; nt < 4; nt++) {
                int ccol = n0 + warp_n * 32 + nt * 8 + (lane & 3) * 2;
                float2 bb = *(const float2*)&bias[ccol];
                *(float2*)&Cf[(size_t)r * N + ccol] =
                    make_float2(acc[mt][nt][0] + bb.x, acc[mt][nt][1] + bb.y);
                *(float2*)&Cf[(size_t)(r + 8) * N + ccol] =
                    make_float2(acc[mt][nt][2] + bb.x, acc[mt][nt][3] + bb.y);
            }
        }
    }
}

#define GEMM_SMEM64 (2 * (20480 + 2 * 64 * 80))

// ---------------- tensor-core causal flash attention (bf16x3, BM=64, R6) ----------------
#define FA_STRIDE 144
#define FA_QTILE  9216
#define FA_STAGE  (4 * FA_QTILE)
#define FA_SMEM   (2 * FA_QTILE + 2 * FA_STAGE)

__device__ __forceinline__ void fa_load_kv(uint32_t dst,
                                           const bf16* qh_, const bf16* ql_,
                                           size_t kbase, int tid) {
    #pragma unroll
    for (int i = 0; i < 16; i++) {
        const int t = i >> 2;
        int g = tid + (i & 3) * 128;
        int r = g >> 3, c = g & 7;
        const bf16* base = (t & 1) ? ql_ : qh_;
        const bf16* src = base + kbase + ((t >> 1) ? (size_t)DIM : (size_t)0)
                          + (size_t)r * TD + c * 8;
        CP_ASYNC16(dst + t * FA_QTILE + r * FA_STRIDE + c * 16, src);
    }
}

__global__ __launch_bounds__(128)
void flash_attn_tc(const bf16* __restrict__ qh_, const bf16* __restrict__ ql_,
                   bf16* __restrict__ oh_, bf16* __restrict__ ol_) {
    extern __shared__ char dsm[];
    uint32_t sb = smem_u32(dsm);
    const int qb = gridDim.x - 1 - blockIdx.x;
    const int bh = blockIdx.y;
    const int b = bh / NH, hh = bh % NH;
    const int tid = threadIdx.x, lane = tid & 31, w = tid >> 5;
    const int wrow = w * 16;

    {
        size_t qrow0 = ((size_t)(b * SEQ + qb * 64)) * TD + hh * HD;
        #pragma unroll
        for (int i = 0; i < 8; i++) {
            const int t = i >> 2;
            int g = tid + (i & 3) * 128;
            int r = g >> 3, c = g & 7;
            const bf16* src = (t ? ql_ : qh_) + qrow0 + (size_t)r * TD + c * 8;
            CP_ASYNC16(sb + t * FA_QTILE + r * FA_STRIDE + c * 16, src);
        }
    }
    fa_load_kv(sb + 2 * FA_QTILE, qh_, ql_,
               ((size_t)(b * SEQ)) * TD + DIM + hh * HD, tid);
    CP_COMMIT();

    const uint32_t lmA = sb + (uint32_t)((wrow + (lane & 7) + ((lane >> 3) & 1) * 8) * FA_STRIDE
                                         + ((lane >> 4) & 1) * 16);
    const uint32_t lmB = (uint32_t)((lane & 15) * FA_STRIDE + ((lane >> 4) & 1) * 16);
    const uint32_t lmV = lmB;

    float oacc[8][4] = {};
    float mi[2] = { -1e30f, -1e30f };
    float li[2] = { 0.0f, 0.0f };

    for (int kt = 0; kt <= qb; kt++) {
        CP_WAIT0();
        __syncthreads();
        if (kt < qb) {
            fa_load_kv(sb + 2 * FA_QTILE + ((kt + 1) & 1) * FA_STAGE, qh_, ql_,
                       ((size_t)(b * SEQ + (kt + 1) * 64)) * TD + DIM + hh * HD, tid);
            CP_COMMIT();
        }
        const uint32_t stg = sb + 2 * FA_QTILE + (uint32_t)((kt & 1) * FA_STAGE);
        const uint32_t sK = stg, sV = stg + 2 * FA_QTILE;

        float sacc[8][4] = {};
        #pragma unroll
        for (int ks = 0; ks < 4; ks++) {
            uint32_t qhf[4], qlf[4];
            LDSM4(qhf[0], qhf[1], qhf[2], qhf[3], lmA + ks * 32);
            LDSM4(qlf[0], qlf[1], qlf[2], qlf[3], lmA + FA_QTILE + ks * 32);
            #pragma unroll
            for (int jp = 0; jp < 4; jp++) {
                uint32_t r0, r1, r2, r3;
                uint32_t bh0[2], bh1[2], bl0[2], bl1[2];
                uint32_t kb = sK + (uint32_t)(jp * 16 * FA_STRIDE) + lmB + ks * 32;
                LDSM4(r0, r1, r2, r3, kb);
                bh0[0] = r0; bh0[1] = r2; bh1[0] = r1; bh1[1] = r3;
                LDSM4(r0, r1, r2, r3, kb + FA_QTILE);
                bl0[0] = r0; bl0[1] = r2; bl1[0] = r1; bl1[1] = r3;
                MMA16816(sacc[2 * jp],     qhf, bh0);
                MMA16816(sacc[2 * jp],     qhf, bl0);
                MMA16816(sacc[2 * jp],     qlf, bh0);
                MMA16816(sacc[2 * jp + 1], qhf, bh1);
                MMA16816(sacc[2 * jp + 1], qhf, bl1);
                MMA16816(sacc[2 * jp + 1], qlf, bh1);
            }
        }

        if (kt == qb) {
            #pragma unroll
            for (int nt = 0; nt < 8; nt++)
                #pragma unroll
                for (int e = 0; e < 4; e++) {
                    int jl = nt * 8 + (lane & 3) * 2 + (e & 1);
                    int il = wrow + (lane >> 2) + (e >> 1) * 8;
                    float s = sacc[nt][e];
                    sacc[nt][e] = (jl <= il) ? s * 0.125f : -1e4f;
                }
        } else {
            #pragma unroll
            for (int nt = 0; nt < 8; nt++)
                #pragma unroll
                for (int e = 0; e < 4; e++)
                    sacc[nt][e] *= 0.125f;
        }

        #pragma unroll
        for (int hf = 0; hf < 2; hf++) {
            const int e0 = hf * 2;
            float mx = -1e30f;
            #pragma unroll
            for (int nt = 0; nt < 8; nt++)
                mx = fmaxf(mx, fmaxf(sacc[nt][e0], sacc[nt][e0 + 1]));
            mx = fmaxf(mx, __shfl_xor_sync(0xffffffffu, mx, 1));
            mx = fmaxf(mx, __shfl_xor_sync(0xffffffffu, mx, 2));
            float mn = fmaxf(mi[hf], mx);
            float alpha = __expf(mi[hf] - mn);
            float sum = 0.0f;
            #pragma unroll
            for (int nt = 0; nt < 8; nt++) {
                float p0 = __expf(sacc[nt][e0] - mn);
                float p1 = __expf(sacc[nt][e0 + 1] - mn);
                sacc[nt][e0] = p0; sacc[nt][e0 + 1] = p1;
                sum += p0 + p1;
            }
            sum += __shfl_xor_sync(0xffffffffu, sum, 1);
            sum += __shfl_xor_sync(0xffffffffu, sum, 2);
            li[hf] = li[hf] * alpha + sum;
            mi[hf] = mn;
            #pragma unroll
            for (int nt = 0; nt < 8; nt++) {
                oacc[nt][e0]     *= alpha;
                oacc[nt][e0 + 1] *= alpha;
            }
        }

        #pragma unroll
        for (int kk = 0; kk < 4; kk++) {
            uint32_t ph[4], pl[4];
            split2(sacc[2 * kk][0],     sacc[2 * kk][1],     ph[0], pl[0]);
            split2(sacc[2 * kk][2],     sacc[2 * kk][3],     ph[1], pl[1]);
            split2(sacc[2 * kk + 1][0], sacc[2 * kk + 1][1], ph[2], pl[2]);
            split2(sacc[2 * kk + 1][2], sacc[2 * kk + 1][3], ph[3], pl[3]);
            #pragma unroll
            for (int dp = 0; dp < 4; dp++) {
                uint32_t h0, h1, h2, h3, l0, l1, l2, l3;
                uint32_t vb = sV + (uint32_t)(kk * 16 * FA_STRIDE + dp * 32) + lmV;
                LDSM4T(h0, h1, h2, h3, vb);
                LDSM4T(l0, l1, l2, l3, vb + FA_QTILE);
                uint32_t vh0[2] = { h0, h1 }, vh1[2] = { h2, h3 };
                uint32_t vl0[2] = { l0, l1 }, vl1[2] = { l2, l3 };
                MMA16816(oacc[2 * dp],     ph, vh0);
                MMA16816(oacc[2 * dp],     ph, vl0);
                MMA16816(oacc[2 * dp],     pl, vh0);
                MMA16816(oacc[2 * dp + 1], ph, vh1);
                MMA16816(oacc[2 * dp + 1], ph, vl1);
                MMA16816(oacc[2 * dp + 1], pl, vh1);
            }
        }
    }

    const float inv0 = 1.0f / li[0], inv1 = 1.0f / li[1];
    const int i0 = qb * 64 + wrow + (lane >> 2);
    const size_t row0 = ((size_t)(b * SEQ) + i0) * DIM + hh * HD;
    const size_t row1 = row0 + (size_t)8 * DIM;
    #pragma unroll
    for (int nt = 0; nt < 8; nt++) {
        int d = nt * 8 + (lane & 3) * 2;
        uint32_t hi, lo;
        split2(oacc[nt][0] * inv0, oacc[nt][1] * inv0, hi, lo);
        *(uint32_t*)&oh_[row0 + d] = hi;
        *(uint32_t*)&ol_[row0 + d] = lo;
        split2(oacc[nt][2] * inv1, oacc[nt][3] * inv1, hi, lo);
        *(uint32_t*)&oh_[row1 + d] = hi;
        *(uint32_t*)&ol_[row1 + d] = lo;
    }
}

// ---------------- fused residual + layernorm ----------------
__global__ __launch_bounds__(256)
void add_ln(const float* __restrict__ x, const float* __restrict__ y,
            const float* __restrict__ w, const float* __restrict__ bvec,
            float* __restrict__ out,
            bf16* __restrict__ oh, bf16* __restrict__ ol) {
    int row = blockIdx.x;
    int tid = threadIdx.x;
    const float* xr = x + (size_t)row * DIM;
    const float* yr = y + (size_t)row * DIM;
    float v[3];
    float s = 0.0f;
    #pragma unroll
    for (int i = 0; i < 3; i++) {
        int c = tid + i * 256;
        v[i] = xr[c] + yr[c];
        s += v[i];
    }
    __shared__ float red[8];
    #pragma unroll
    for (int o = 16; o; o >>= 1) s += __shfl_xor_sync(0xffffffffu, s, o);
    if ((tid & 31) == 0) red[tid >> 5] = s;
    __syncthreads();
    float tot = 0.0f;
    #pragma unroll
    for (int i = 0; i < 8; i++) tot += red[i];
    float mu = tot * (1.0f / DIM);

    float s2 = 0.0f;
    #pragma unroll
    for (int i = 0; i < 3; i++) {
        float d = v[i] - mu;
        s2 += d * d;
    }
    __syncthreads();
    #pragma unroll
    for (int o = 16; o; o >>= 1) s2 += __shfl_xor_sync(0xffffffffu, s2, o);
    if ((tid & 31) == 0) red[tid >> 5] = s2;
    __syncthreads();
    float tot2 = 0.0f;
    #pragma unroll
    for (int i = 0; i < 8; i++) tot2 += red[i];
    float rinv = rsqrtf(tot2 * (1.0f / DIM) + 1e-5f);

    #pragma unroll
    for (int i = 0; i < 3; i++) {
        int c = tid + i * 256;
        float val = (v[i] - mu) * rinv * w[c] + bvec[c];
        size_t off = (size_t)row * DIM + c;
        out[off] = val;
        if (oh) {
            bf16 h = __float2bfloat16_rn(val);
            oh[off] = h;
            ol[off] = __float2bfloat16_rn(val - __bfloat162float(h));
        }
    }
}

// ---------------- launch ----------------
extern "C" void kernel_launch(void* const* d_in, const int* in_sizes, int n_in,
                              void* d_out, int out_size) {
    (void)in_sizes; (void)n_in; (void)out_size;
    const int*   ids      = (const int*)  d_in[0];
    const float* tok_emb  = (const float*)d_in[3];
    const float* pos_emb  = (const float*)d_in[4];
    const float* c_attn_w = (const float*)d_in[5];
    const float* c_attn_b = (const float*)d_in[6];
    const float* c_proj_w = (const float*)d_in[7];
    const float* c_proj_b = (const float*)d_in[8];
    const float* ln1_w    = (const float*)d_in[9];
    const float* ln1_b    = (const float*)d_in[10];
    const float* c_fc_w   = (const float*)d_in[11];
    const float* c_fc_b   = (const float*)d_in[12];
    const float* mlp_w    = (const float*)d_in[13];
    const float* mlp_b    = (const float*)d_in[14];
    const float* ln2_w    = (const float*)d_in[15];
    const float* ln2_b    = (const float*)d_in[16];
    float* out = (float*)d_out;

    float *h, *a, *n, *m;
    bf16 *hh, *hl, *qkvh, *qkvl, *ath, *atl, *nh, *nl, *fch, *fcl;
    bf16 *wqh, *wql, *wph, *wpl, *wfh, *wfl, *wmh, *wml;
    cudaGetSymbolAddress((void**)&h,    g_h);
    cudaGetSymbolAddress((void**)&a,    g_a);
    cudaGetSymbolAddress((void**)&n,    g_n);
    cudaGetSymbolAddress((void**)&m,    g_m);
    cudaGetSymbolAddress((void**)&hh,   g_hh);
    cudaGetSymbolAddress((void**)&hl,   g_hl);
    cudaGetSymbolAddress((void**)&qkvh, g_qkvh);
    cudaGetSymbolAddress((void**)&qkvl, g_qkvl);
    cudaGetSymbolAddress((void**)&ath,  g_ath);
    cudaGetSymbolAddress((void**)&atl,  g_atl);
    cudaGetSymbolAddress((void**)&nh,   g_nh);
    cudaGetSymbolAddress((void**)&nl,   g_nl);
    cudaGetSymbolAddress((void**)&fch,  g_fch);
    cudaGetSymbolAddress((void**)&fcl,  g_fcl);
    cudaGetSymbolAddress((void**)&wqh,  g_wqh);
    cudaGetSymbolAddress((void**)&wql,  g_wql);
    cudaGetSymbolAddress((void**)&wph,  g_wph);
    cudaGetSymbolAddress((void**)&wpl,  g_wpl);
    cudaGetSymbolAddress((void**)&wfh,  g_wfh);
    cudaGetSymbolAddress((void**)&wfl,  g_wfl);
    cudaGetSymbolAddress((void**)&wmh,  g_wmh);
    cudaGetSymbolAddress((void**)&wml,  g_wml);

    cudaFuncSetAttribute(gemm_p128<1>, cudaFuncAttributeMaxDynamicSharedMemorySize, GEMM_SMEM128);
    cudaFuncSetAttribute(gemm_p128<2>, cudaFuncAttributeMaxDynamicSharedMemorySize, GEMM_SMEM128);
    cudaFuncSetAttribute(gemm_p64,     cudaFuncAttributeMaxDynamicSharedMemorySize, GEMM_SMEM64);
    cudaFuncSetAttribute(flash_attn_tc, cudaFuncAttributeMaxDynamicSharedMemorySize, FA_SMEM);

    transpose_conv<<<dim3(TD / 32, DIM / 32, NLAYER), 256>>>(c_attn_w, wqh, wql, DIM, TD);
    transpose_conv<<<dim3(DIM / 32, DIM / 32, NLAYER), 256>>>(c_proj_w, wph, wpl, DIM, DIM);
    transpose_conv<<<dim3(FD / 32, DIM / 32, NLAYER), 256>>>(c_fc_w, wfh, wfl, DIM, FD);
    transpose_conv<<<dim3(DIM / 32, FD / 32, NLAYER), 256>>>(mlp_w, wmh, wml, FD, DIM);

    embed_kernel<<<MTOK * DIM / 4 / 256, 256>>>(ids, tok_emb, pos_emb, h, hh, hl);

    for (int l = 0; l < NLAYER; l++) {
        // qkv: [4096,768] @ [768,2304] -> split bf16 (576 tiles, 4-stage pipeline)
        gemm_p128<1><<<296, 256, GEMM_SMEM128>>>(
            hh, hl, wqh + (size_t)l * TD * DIM, wql + (size_t)l * TD * DIM,
            c_attn_b + (size_t)l * TD, nullptr, qkvh, qkvl, MTOK, TD, DIM);

        flash_attn_tc<<<dim3(SEQ / 64, BATCH * NH), 128, FA_SMEM>>>(qkvh, qkvl, ath, atl);

        // proj: [4096,768] @ [768,768] -> fp32 (384 tiles of 128x64)
        gemm_p64<<<384, 128, GEMM_SMEM64>>>(
            ath, atl, wph + (size_t)l * DIM * DIM, wpl + (size_t)l * DIM * DIM,
            c_proj_b + (size_t)l * DIM, a, MTOK, DIM, DIM);

        add_ln<<<MTOK, 256>>>(h, a, ln1_w + (size_t)l * DIM, ln1_b + (size_t)l * DIM,
                              n, nh, nl);

        // fc: [4096,768] @ [768,3072] + gelu -> split bf16 (768 tiles, 4-stage pipeline)
        gemm_p128<2><<<296, 256, GEMM_SMEM128>>>(
            nh, nl, wfh + (size_t)l * FD * DIM, wfl + (size_t)l * FD * DIM,
            c_fc_b + (size_t)l * FD, nullptr, fch, fcl, MTOK, FD, DIM);

        // mlp: [4096,3072] @ [3072,768] -> fp32 (384 tiles of 128x64)
        gemm_p64<<<384, 128, GEMM_SMEM64>>>(
            fch, fcl, wmh + (size_t)l * DIM * FD, wml + (size_t)l * DIM * FD,
            mlp_b + (size_t)l * DIM, m, MTOK, DIM, FD);

        bool last = (l == NLAYER - 1);
        add_ln<<<MTOK, 256>>>(n, m, ln2_w + (size_t)l * DIM, ln2_b + (size_t)l * DIM,
                              last ? out : h,
                              last ? nullptr : hh, last ? nullptr : hl);
    }
}

// round 12
// speedup vs baseline: 1.0780x; 1.0780x over previous
#include <cuda_runtime.h>
#include <cuda_bf16.h>
#include <math.h>
#include <stdint.h>

#define NLAYER 5
#define BATCH 4
#define SEQ 1024
#define DIM 768
#define NH 12
#define HD 64
#define TD (3*DIM)
#define FD (4*DIM)
#define MTOK (BATCH*SEQ)   /* 4096 */

typedef __nv_bfloat16 bf16;

// ---------------- scratch (no allocations allowed) ----------------
__device__ float g_h[MTOK*DIM];
__device__ float g_a[MTOK*DIM];
__device__ float g_n[MTOK*DIM];
__device__ float g_m[MTOK*DIM];
__device__ __align__(128) bf16 g_hh[MTOK*DIM],  g_hl[MTOK*DIM];
__device__ __align__(128) bf16 g_qkvh[MTOK*TD], g_qkvl[MTOK*TD];
__device__ __align__(128) bf16 g_ath[MTOK*DIM], g_atl[MTOK*DIM];
__device__ __align__(128) bf16 g_nh[MTOK*DIM],  g_nl[MTOK*DIM];
__device__ __align__(128) bf16 g_fch[MTOK*FD],  g_fcl[MTOK*FD];
// all-layer transposed weights (hi/lo)
__device__ __align__(128) bf16 g_wqh[NLAYER*TD*DIM],  g_wql[NLAYER*TD*DIM];
__device__ __align__(128) bf16 g_wph[NLAYER*DIM*DIM], g_wpl[NLAYER*DIM*DIM];
__device__ __align__(128) bf16 g_wfh[NLAYER*FD*DIM],  g_wfl[NLAYER*FD*DIM];
__device__ __align__(128) bf16 g_wmh[NLAYER*DIM*FD],  g_wml[NLAYER*DIM*FD];

// ---------------- helpers ----------------
__device__ __forceinline__ uint32_t smem_u32(const void* p) {
    uint32_t a;
    asm("{ .reg .u64 t; cvta.to.shared.u64 t, %1; cvt.u32.u64 %0, t; }" : "=r"(a) : "l"(p));
    return a;
}

#define LDSM4(r0, r1, r2, r3, a) \
    asm volatile("ldmatrix.sync.aligned.m8n8.x4.shared.b16 {%0,%1,%2,%3}, [%4];" \
                 : "=r"(r0), "=r"(r1), "=r"(r2), "=r"(r3) : "r"(a))
#define LDSM4T(r0, r1, r2, r3, a) \
    asm volatile("ldmatrix.sync.aligned.m8n8.x4.trans.shared.b16 {%0,%1,%2,%3}, [%4];" \
                 : "=r"(r0), "=r"(r1), "=r"(r2), "=r"(r3) : "r"(a))

#define MMA16816(d, a, b) \
    asm volatile("mma.sync.aligned.m16n8k16.row.col.f32.bf16.bf16.f32 " \
                 "{%0,%1,%2,%3},{%4,%5,%6,%7},{%8,%9},{%0,%1,%2,%3};" \
                 : "+f"((d)[0]), "+f"((d)[1]), "+f"((d)[2]), "+f"((d)[3]) \
                 : "r"((a)[0]), "r"((a)[1]), "r"((a)[2]), "r"((a)[3]), \
                   "r"((b)[0]), "r"((b)[1]))

#define CP_ASYNC16(dst, src) \
    asm volatile("cp.async.cg.shared.global [%0], [%1], 16;" :: "r"(dst), "l"(src) : "memory")
#define CP_COMMIT() asm volatile("cp.async.commit_group;" ::: "memory")
#define CP_WAIT0()  asm volatile("cp.async.wait_group 0;" ::: "memory")

__device__ __forceinline__ uint32_t pk(bf16 a, bf16 b) {
    __nv_bfloat162 v(a, b);
    return *(uint32_t*)&v;
}
__device__ __forceinline__ void split2(float x0, float x1, uint32_t& hi, uint32_t& lo) {
    bf16 h0 = __float2bfloat16_rn(x0);
    bf16 h1 = __float2bfloat16_rn(x1);
    bf16 l0 = __float2bfloat16_rn(x0 - __bfloat162float(h0));
    bf16 l1 = __float2bfloat16_rn(x1 - __bfloat162float(h1));
    hi = pk(h0, h1); lo = pk(l0, l1);
}

__device__ __forceinline__ float gelu_f(float x) {
    float x3 = x * x * x;
    return 0.5f * x * (1.0f + tanhf(0.7978845608028654f * (x + 0.044715f * x3)));
}

// ---------------- embedding (fp32 + split bf16) ----------------
__global__ void embed_kernel(const int* __restrict__ ids,
                             const float* __restrict__ tok_emb,
                             const float* __restrict__ pos_emb,
                             float* __restrict__ out,
                             bf16* __restrict__ oh, bf16* __restrict__ ol) {
    int idx = blockIdx.x * blockDim.x + threadIdx.x;
    if (idx >= MTOK * DIM / 4) return;
    int d4  = idx % (DIM / 4);
    int bs  = idx / (DIM / 4);
    int s   = bs % SEQ;
    int tok = ids[bs];
    float4 t = *(const float4*)&tok_emb[(size_t)tok * DIM + d4 * 4];
    float4 p = *(const float4*)&pos_emb[(size_t)s   * DIM + d4 * 4];
    float4 o = make_float4(t.x + p.x, t.y + p.y, t.z + p.z, t.w + p.w);
    size_t off = (size_t)bs * DIM + d4 * 4;
    *(float4*)&out[off] = o;
    uint32_t h01, l01, h23, l23;
    split2(o.x, o.y, h01, l01);
    split2(o.z, o.w, h23, l23);
    *(uint32_t*)&oh[off]     = h01; *(uint32_t*)&oh[off + 2] = h23;
    *(uint32_t*)&ol[off]     = l01; *(uint32_t*)&ol[off + 2] = l23;
}

// ---------------- batched transpose + fp32 -> bf16 hi/lo split ----------------
__global__ __launch_bounds__(256)
void transpose_conv(const float* __restrict__ W,
                    bf16* __restrict__ Th, bf16* __restrict__ Tl,
                    int K, int N) {
    __shared__ float t[32][33];
    const size_t lw = (size_t)blockIdx.z * K * N;
    const float* Wl = W + lw;
    bf16* Thl = Th + lw;
    bf16* Tll = Tl + lw;
    int n0 = blockIdx.x * 32, k0 = blockIdx.y * 32;
    int tx = threadIdx.x & 31, ty = threadIdx.x >> 5;
    #pragma unroll
    for (int i = 0; i < 4; i++)
        t[ty + i * 8][tx] = Wl[(size_t)(k0 + ty + i * 8) * N + n0 + tx];
    __syncthreads();
    #pragma unroll
    for (int i = 0; i < 4; i++) {
        float v = t[tx][ty + i * 8];
        bf16 h = __float2bfloat16_rn(v);
        bf16 l = __float2bfloat16_rn(v - __bfloat162float(h));
        size_t off = (size_t)(n0 + ty + i * 8) * K + k0 + tx;
        Thl[off] = h;
        Tll[off] = l;
    }
}

// ---------------- bf16x3 persistent tensor-core GEMM (R6 config) ----------------
template<int NB>
__device__ __forceinline__ void load_stage(uint32_t dst,
        const bf16* A0, const bf16* A1, const bf16* B0, const bf16* B1,
        int K, int kcol, int tid) {
    if (NB == 128) {
        #pragma unroll
        for (int i = 0; i < 8; i++) {
            const int t = i >> 1;
            int g = tid + (i & 1) * 256;
            int r = g >> 2, c = g & 3;
            const bf16* src = (t == 0 ? A0 : t == 1 ? A1 : t == 2 ? B0 : B1)
                              + (size_t)r * K + kcol + c * 8;
            CP_ASYNC16(dst + t * 10240 + r * 80 + c * 16, src);
        }
    } else {  // NB==64, 128 threads
        #pragma unroll
        for (int i = 0; i < 8; i++) {
            const int sel = i >> 2;
            int g = tid + (i & 3) * 128;
            int r = g >> 2, c = g & 3;
            const bf16* src = (sel ? A1 : A0) + (size_t)r * K + kcol + c * 8;
            CP_ASYNC16(dst + sel * 10240 + r * 80 + c * 16, src);
        }
        #pragma unroll
        for (int i = 0; i < 4; i++) {
            const int sel = i >> 1;
            int g = tid + (i & 1) * 128;
            int r = g >> 2, c = g & 3;
            const bf16* src = (sel ? B1 : B0) + (size_t)r * K + kcol + c * 8;
            CP_ASYNC16(dst + 20480 + sel * (NB * 80) + r * 80 + c * 16, src);
        }
    }
}

// EPI: 0 = fp32 out + residual, 1 = split out, 2 = split out + gelu
template<int EPI, int NB>
__global__ __launch_bounds__(NB == 128 ? 256 : 128, NB == 128 ? 2 : 3)
void gemm_p(const bf16* __restrict__ Ah, const bf16* __restrict__ Al,
            const bf16* __restrict__ Bh, const bf16* __restrict__ Bl,
            const float* __restrict__ bias, const float* __restrict__ Res,
            float* __restrict__ Cf,
            bf16* __restrict__ Ch, bf16* __restrict__ Cl,
            int M, int N, int K) {
    constexpr uint32_t OAL = 10240;
    constexpr uint32_t OBH = 20480;
    constexpr uint32_t OBL = 20480 + NB * 80;
    constexpr uint32_t BUF = 20480 + 2 * NB * 80;
    extern __shared__ char dsm[];
    uint32_t sb = smem_u32(dsm);
    const int tid = threadIdx.x;
    const int lane = tid & 31, wid = tid >> 5;
    const int warp_m = wid & 1;
    const int warp_n = wid >> 1;
    const uint32_t lm_off = (uint32_t)(((lane & 7) + ((lane >> 3) & 1) * 8) * 80
                                       + ((lane >> 4) & 1) * 16);
    const int nk = K >> 5;
    const int mtiles = M >> 7;
    const int tiles = mtiles * (N / NB);

    for (int t = blockIdx.x; t < tiles; t += gridDim.x) {
        const int m0 = (t % mtiles) << 7;
        const int n0 = (t / mtiles) * NB;
        const bf16* tA0 = Ah + (size_t)m0 * K;
        const bf16* tA1 = Al + (size_t)m0 * K;
        const bf16* tB0 = Bh + (size_t)n0 * K;
        const bf16* tB1 = Bl + (size_t)n0 * K;

        load_stage<NB>(sb, tA0, tA1, tB0, tB1, K, 0, tid);
        CP_COMMIT();

        float acc[4][4][4] = {};
        for (int kc = 0; kc < nk; kc++) {
            CP_WAIT0();
            __syncthreads();
            if (kc + 1 < nk) {
                load_stage<NB>(sb + ((kc + 1) & 1) * BUF, tA0, tA1, tB0, tB1,
                               K, (kc + 1) * 32, tid);
                CP_COMMIT();
            }
            const uint32_t sA = sb + (uint32_t)((kc & 1) * BUF);
            #pragma unroll
            for (int ks = 0; ks < 2; ks++) {
                uint32_t ah[4][4], al[4][4], bh[4][2], bl[4][2];
                // pass 1: Ah x Bh
                #pragma unroll
                for (int mt = 0; mt < 4; mt++) {
                    uint32_t ad = sA + (uint32_t)((warp_m * 64 + mt * 16) * 80 + ks * 32) + lm_off;
                    LDSM4(ah[mt][0], ah[mt][1], ah[mt][2], ah[mt][3], ad);
                }
                #pragma unroll
                for (int ntp = 0; ntp < 2; ntp++) {
                    uint32_t bd = sA + OBH +
                                  (uint32_t)((warp_n * 32 + ntp * 16) * 80 + ks * 32) + lm_off;
                    uint32_t r0, r1, r2, r3;
                    LDSM4(r0, r1, r2, r3, bd);
                    bh[2 * ntp][0] = r0; bh[2 * ntp][1] = r2;
                    bh[2 * ntp + 1][0] = r1; bh[2 * ntp + 1][1] = r3;
                }
                #pragma unroll
                for (int mt = 0; mt < 4; mt++)
                    #pragma unroll
                    for (int nt = 0; nt < 4; nt++)
                        MMA16816(acc[mt][nt], ah[mt], bh[nt]);
                // pass 2: Ah x Bl
                #pragma unroll
                for (int ntp = 0; ntp < 2; ntp++) {
                    uint32_t bd = sA + OBL +
                                  (uint32_t)((warp_n * 32 + ntp * 16) * 80 + ks * 32) + lm_off;
                    uint32_t r0, r1, r2, r3;
                    LDSM4(r0, r1, r2, r3, bd);
                    bl[2 * ntp][0] = r0; bl[2 * ntp][1] = r2;
                    bl[2 * ntp + 1][0] = r1; bl[2 * ntp + 1][1] = r3;
                }
                #pragma unroll
                for (int mt = 0; mt < 4; mt++)
                    #pragma unroll
                    for (int nt = 0; nt < 4; nt++)
                        MMA16816(acc[mt][nt], ah[mt], bl[nt]);
                // pass 3: Al x Bh
                #pragma unroll
                for (int mt = 0; mt < 4; mt++) {
                    uint32_t ad = sA + OAL +
                                  (uint32_t)((warp_m * 64 + mt * 16) * 80 + ks * 32) + lm_off;
                    LDSM4(al[mt][0], al[mt][1], al[mt][2], al[mt][3], ad);
                }
                #pragma unroll
                for (int mt = 0; mt < 4; mt++)
                    #pragma unroll
                    for (int nt = 0; nt < 4; nt++)
                        MMA16816(acc[mt][nt], al[mt], bh[nt]);
            }
        }

        // epilogue
        #pragma unroll
        for (int mt = 0; mt < 4; mt++) {
            int r = m0 + warp_m * 64 + mt * 16 + (lane >> 2);
            #pragma unroll
            for (int nt = 0; nt < 4; nt++) {
                int ccol = n0 + warp_n * 32 + nt * 8 + (lane & 3) * 2;
                float2 bb = *(const float2*)&bias[ccol];
                float x0 = acc[mt][nt][0] + bb.x;
                float x1 = acc[mt][nt][1] + bb.y;
                float x2 = acc[mt][nt][2] + bb.x;
                float x3 = acc[mt][nt][3] + bb.y;
                if (EPI == 2) { x0 = gelu_f(x0); x1 = gelu_f(x1); x2 = gelu_f(x2); x3 = gelu_f(x3); }
                if (EPI == 0) {
                    // fused residual add
                    float2 r0 = *(const float2*)&Res[(size_t)r * N + ccol];
                    float2 r1 = *(const float2*)&Res[(size_t)(r + 8) * N + ccol];
                    *(float2*)&Cf[(size_t)r * N + ccol] =
                        make_float2(x0 + r0.x, x1 + r0.y);
                    *(float2*)&Cf[(size_t)(r + 8) * N + ccol] =
                        make_float2(x2 + r1.x, x3 + r1.y);
                } else {
                    uint32_t hi, lo;
                    split2(x0, x1, hi, lo);
                    *(uint32_t*)&Ch[(size_t)r * N + ccol] = hi;
                    *(uint32_t*)&Cl[(size_t)r * N + ccol] = lo;
                    split2(x2, x3, hi, lo);
                    *(uint32_t*)&Ch[(size_t)(r + 8) * N + ccol] = hi;
                    *(uint32_t*)&Cl[(size_t)(r + 8) * N + ccol] = lo;
                }
            }
        }
    }
}

#define GEMM_SMEM128 (2 * (20480 + 2 * 128 * 80))
#define GEMM_SMEM64  (2 * (20480 + 2 * 64 * 80))

// ---------------- tensor-core causal flash attention (bf16x3, BM=64, R6) ----------------
#define FA_STRIDE 144
#define FA_QTILE  9216
#define FA_STAGE  (4 * FA_QTILE)
#define FA_SMEM   (2 * FA_QTILE + 2 * FA_STAGE)

__device__ __forceinline__ void fa_load_kv(uint32_t dst,
                                           const bf16* qh_, const bf16* ql_,
                                           size_t kbase, int tid) {
    #pragma unroll
    for (int i = 0; i < 16; i++) {
        const int t = i >> 2;
        int g = tid + (i & 3) * 128;
        int r = g >> 3, c = g & 7;
        const bf16* base = (t & 1) ? ql_ : qh_;
        const bf16* src = base + kbase + ((t >> 1) ? (size_t)DIM : (size_t)0)
                          + (size_t)r * TD + c * 8;
        CP_ASYNC16(dst + t * FA_QTILE + r * FA_STRIDE + c * 16, src);
    }
}

__global__ __launch_bounds__(128)
void flash_attn_tc(const bf16* __restrict__ qh_, const bf16* __restrict__ ql_,
                   bf16* __restrict__ oh_, bf16* __restrict__ ol_) {
    extern __shared__ char dsm[];
    uint32_t sb = smem_u32(dsm);
    const int qb = gridDim.x - 1 - blockIdx.x;
    const int bh = blockIdx.y;
    const int b = bh / NH, hh = bh % NH;
    const int tid = threadIdx.x, lane = tid & 31, w = tid >> 5;
    const int wrow = w * 16;

    {
        size_t qrow0 = ((size_t)(b * SEQ + qb * 64)) * TD + hh * HD;
        #pragma unroll
        for (int i = 0; i < 8; i++) {
            const int t = i >> 2;
            int g = tid + (i & 3) * 128;
            int r = g >> 3, c = g & 7;
            const bf16* src = (t ? ql_ : qh_) + qrow0 + (size_t)r * TD + c * 8;
            CP_ASYNC16(sb + t * FA_QTILE + r * FA_STRIDE + c * 16, src);
        }
    }
    fa_load_kv(sb + 2 * FA_QTILE, qh_, ql_,
               ((size_t)(b * SEQ)) * TD + DIM + hh * HD, tid);
    CP_COMMIT();

    const uint32_t lmA = sb + (uint32_t)((wrow + (lane & 7) + ((lane >> 3) & 1) * 8) * FA_STRIDE
                                         + ((lane >> 4) & 1) * 16);
    const uint32_t lmB = (uint32_t)((lane & 15) * FA_STRIDE + ((lane >> 4) & 1) * 16);
    const uint32_t lmV = lmB;

    float oacc[8][4] = {};
    float mi[2] = { -1e30f, -1e30f };
    float li[2] = { 0.0f, 0.0f };

    for (int kt = 0; kt <= qb; kt++) {
        CP_WAIT0();
        __syncthreads();
        if (kt < qb) {
            fa_load_kv(sb + 2 * FA_QTILE + ((kt + 1) & 1) * FA_STAGE, qh_, ql_,
                       ((size_t)(b * SEQ + (kt + 1) * 64)) * TD + DIM + hh * HD, tid);
            CP_COMMIT();
        }
        const uint32_t stg = sb + 2 * FA_QTILE + (uint32_t)((kt & 1) * FA_STAGE);
        const uint32_t sK = stg, sV = stg + 2 * FA_QTILE;

        float sacc[8][4] = {};
        #pragma unroll
        for (int ks = 0; ks < 4; ks++) {
            uint32_t qhf[4], qlf[4];
            LDSM4(qhf[0], qhf[1], qhf[2], qhf[3], lmA + ks * 32);
            LDSM4(qlf[0], qlf[1], qlf[2], qlf[3], lmA + FA_QTILE + ks * 32);
            #pragma unroll
            for (int jp = 0; jp < 4; jp++) {
                uint32_t r0, r1, r2, r3;
                uint32_t bh0[2], bh1[2], bl0[2], bl1[2];
                uint32_t kb = sK + (uint32_t)(jp * 16 * FA_STRIDE) + lmB + ks * 32;
                LDSM4(r0, r1, r2, r3, kb);
                bh0[0] = r0; bh0[1] = r2; bh1[0] = r1; bh1[1] = r3;
                LDSM4(r0, r1, r2, r3, kb + FA_QTILE);
                bl0[0] = r0; bl0[1] = r2; bl1[0] = r1; bl1[1] = r3;
                MMA16816(sacc[2 * jp],     qhf, bh0);
                MMA16816(sacc[2 * jp],     qhf, bl0);
                MMA16816(sacc[2 * jp],     qlf, bh0);
                MMA16816(sacc[2 * jp + 1], qhf, bh1);
                MMA16816(sacc[2 * jp + 1], qhf, bl1);
                MMA16816(sacc[2 * jp + 1], qlf, bh1);
            }
        }

        if (kt == qb) {
            #pragma unroll
            for (int nt = 0; nt < 8; nt++)
                #pragma unroll
                for (int e = 0; e < 4; e++) {
                    int jl = nt * 8 + (lane & 3) * 2 + (e & 1);
                    int il = wrow + (lane >> 2) + (e >> 1) * 8;
                    float s = sacc[nt][e];
                    sacc[nt][e] = (jl <= il) ? s * 0.125f : -1e4f;
                }
        } else {
            #pragma unroll
            for (int nt = 0; nt < 8; nt++)
                #pragma unroll
                for (int e = 0; e < 4; e++)
                    sacc[nt][e] *= 0.125f;
        }

        #pragma unroll
        for (int hf = 0; hf < 2; hf++) {
            const int e0 = hf * 2;
            float mx = -1e30f;
            #pragma unroll
            for (int nt = 0; nt < 8; nt++)
                mx = fmaxf(mx, fmaxf(sacc[nt][e0], sacc[nt][e0 + 1]));
            mx = fmaxf(mx, __shfl_xor_sync(0xffffffffu, mx, 1));
            mx = fmaxf(mx, __shfl_xor_sync(0xffffffffu, mx, 2));
            float mn = fmaxf(mi[hf], mx);
            float alpha = __expf(mi[hf] - mn);
            float sum = 0.0f;
            #pragma unroll
            for (int nt = 0; nt < 8; nt++) {
                float p0 = __expf(sacc[nt][e0] - mn);
                float p1 = __expf(sacc[nt][e0 + 1] - mn);
                sacc[nt][e0] = p0; sacc[nt][e0 + 1] = p1;
                sum += p0 + p1;
            }
            sum += __shfl_xor_sync(0xffffffffu, sum, 1);
            sum += __shfl_xor_sync(0xffffffffu, sum, 2);
            li[hf] = li[hf] * alpha + sum;
            mi[hf] = mn;
            #pragma unroll
            for (int nt = 0; nt < 8; nt++) {
                oacc[nt][e0]     *= alpha;
                oacc[nt][e0 + 1] *= alpha;
            }
        }

        #pragma unroll
        for (int kk = 0; kk < 4; kk++) {
            uint32_t ph[4], pl[4];
            split2(sacc[2 * kk][0],     sacc[2 * kk][1],     ph[0], pl[0]);
            split2(sacc[2 * kk][2],     sacc[2 * kk][3],     ph[1], pl[1]);
            split2(sacc[2 * kk + 1][0], sacc[2 * kk + 1][1], ph[2], pl[2]);
            split2(sacc[2 * kk + 1][2], sacc[2 * kk + 1][3], ph[3], pl[3]);
            #pragma unroll
            for (int dp = 0; dp < 4; dp++) {
                uint32_t h0, h1, h2, h3, l0, l1, l2, l3;
                uint32_t vb = sV + (uint32_t)(kk * 16 * FA_STRIDE + dp * 32) + lmV;
                LDSM4T(h0, h1, h2, h3, vb);
                LDSM4T(l0, l1, l2, l3, vb + FA_QTILE);
                uint32_t vh0[2] = { h0, h1 }, vh1[2] = { h2, h3 };
                uint32_t vl0[2] = { l0, l1 }, vl1[2] = { l2, l3 };
                MMA16816(oacc[2 * dp],     ph, vh0);
                MMA16816(oacc[2 * dp],     ph, vl0);
                MMA16816(oacc[2 * dp],     pl, vh0);
                MMA16816(oacc[2 * dp + 1], ph, vh1);
                MMA16816(oacc[2 * dp + 1], ph, vl1);
                MMA16816(oacc[2 * dp + 1], pl, vh1);
            }
        }
    }

    const float inv0 = 1.0f / li[0], inv1 = 1.0f / li[1];
    const int i0 = qb * 64 + wrow + (lane >> 2);
    const size_t row0 = ((size_t)(b * SEQ) + i0) * DIM + hh * HD;
    const size_t row1 = row0 + (size_t)8 * DIM;
    #pragma unroll
    for (int nt = 0; nt < 8; nt++) {
        int d = nt * 8 + (lane & 3) * 2;
        uint32_t hi, lo;
        split2(oacc[nt][0] * inv0, oacc[nt][1] * inv0, hi, lo);
        *(uint32_t*)&oh_[row0 + d] = hi;
        *(uint32_t*)&ol_[row0 + d] = lo;
        split2(oacc[nt][2] * inv1, oacc[nt][3] * inv1, hi, lo);
        *(uint32_t*)&oh_[row1 + d] = hi;
        *(uint32_t*)&ol_[row1 + d] = lo;
    }
}

// ---------------- layernorm on pre-summed input (+ optional split) ----------------
__global__ __launch_bounds__(256)
void ln_only(const float* __restrict__ x,
             const float* __restrict__ w, const float* __restrict__ bvec,
             float* __restrict__ out,
             bf16* __restrict__ oh, bf16* __restrict__ ol) {
    int row = blockIdx.x;
    int tid = threadIdx.x;
    const float* xr = x + (size_t)row * DIM;
    float v[3];
    float s = 0.0f;
    #pragma unroll
    for (int i = 0; i < 3; i++) {
        int c = tid + i * 256;
        v[i] = xr[c];
        s += v[i];
    }
    __shared__ float red[8];
    #pragma unroll
    for (int o = 16; o; o >>= 1) s += __shfl_xor_sync(0xffffffffu, s, o);
    if ((tid & 31) == 0) red[tid >> 5] = s;
    __syncthreads();
    float tot = 0.0f;
    #pragma unroll
    for (int i = 0; i < 8; i++) tot += red[i];
    float mu = tot * (1.0f / DIM);

    float s2 = 0.0f;
    #pragma unroll
    for (int i = 0; i < 3; i++) {
        float d = v[i] - mu;
        s2 += d * d;
    }
    __syncthreads();
    #pragma unroll
    for (int o = 16; o; o >>= 1) s2 += __shfl_xor_sync(0xffffffffu, s2, o);
    if ((tid & 31) == 0) red[tid >> 5] = s2;
    __syncthreads();
    float tot2 = 0.0f;
    #pragma unroll
    for (int i = 0; i < 8; i++) tot2 += red[i];
    float rinv = rsqrtf(tot2 * (1.0f / DIM) + 1e-5f);

    #pragma unroll
    for (int i = 0; i < 3; i++) {
        int c = tid + i * 256;
        float val = (v[i] - mu) * rinv * w[c] + bvec[c];
        size_t off = (size_t)row * DIM + c;
        out[off] = val;
        if (oh) {
            bf16 h = __float2bfloat16_rn(val);
            oh[off] = h;
            ol[off] = __float2bfloat16_rn(val - __bfloat162float(h));
        }
    }
}

// ---------------- launch ----------------
extern "C" void kernel_launch(void* const* d_in, const int* in_sizes, int n_in,
                              void* d_out, int out_size) {
    (void)in_sizes; (void)n_in; (void)out_size;
    const int*   ids      = (const int*)  d_in[0];
    const float* tok_emb  = (const float*)d_in[3];
    const float* pos_emb  = (const float*)d_in[4];
    const float* c_attn_w = (const float*)d_in[5];
    const float* c_attn_b = (const float*)d_in[6];
    const float* c_proj_w = (const float*)d_in[7];
    const float* c_proj_b = (const float*)d_in[8];
    const float* ln1_w    = (const float*)d_in[9];
    const float* ln1_b    = (const float*)d_in[10];
    const float* c_fc_w   = (const float*)d_in[11];
    const float* c_fc_b   = (const float*)d_in[12];
    const float* mlp_w    = (const float*)d_in[13];
    const float* mlp_b    = (const float*)d_in[14];
    const float* ln2_w    = (const float*)d_in[15];
    const float* ln2_b    = (const float*)d_in[16];
    float* out = (float*)d_out;

    float *h, *a, *n, *m;
    bf16 *hh, *hl, *qkvh, *qkvl, *ath, *atl, *nh, *nl, *fch, *fcl;
    bf16 *wqh, *wql, *wph, *wpl, *wfh, *wfl, *wmh, *wml;
    cudaGetSymbolAddress((void**)&h,    g_h);
    cudaGetSymbolAddress((void**)&a,    g_a);
    cudaGetSymbolAddress((void**)&n,    g_n);
    cudaGetSymbolAddress((void**)&m,    g_m);
    cudaGetSymbolAddress((void**)&hh,   g_hh);
    cudaGetSymbolAddress((void**)&hl,   g_hl);
    cudaGetSymbolAddress((void**)&qkvh, g_qkvh);
    cudaGetSymbolAddress((void**)&qkvl, g_qkvl);
    cudaGetSymbolAddress((void**)&ath,  g_ath);
    cudaGetSymbolAddress((void**)&atl,  g_atl);
    cudaGetSymbolAddress((void**)&nh,   g_nh);
    cudaGetSymbolAddress((void**)&nl,   g_nl);
    cudaGetSymbolAddress((void**)&fch,  g_fch);
    cudaGetSymbolAddress((void**)&fcl,  g_fcl);
    cudaGetSymbolAddress((void**)&wqh,  g_wqh);
    cudaGetSymbolAddress((void**)&wql,  g_wql);
    cudaGetSymbolAddress((void**)&wph,  g_wph);
    cudaGetSymbolAddress((void**)&wpl,  g_wpl);
    cudaGetSymbolAddress((void**)&wfh,  g_wfh);
    cudaGetSymbolAddress((void**)&wfl,  g_wfl);
    cudaGetSymbolAddress((void**)&wmh,  g_wmh);
    cudaGetSymbolAddress((void**)&wml,  g_wml);

    cudaFuncSetAttribute(gemm_p<1, 128>, cudaFuncAttributeMaxDynamicSharedMemorySize, GEMM_SMEM128);
    cudaFuncSetAttribute(gemm_p<2, 128>, cudaFuncAttributeMaxDynamicSharedMemorySize, GEMM_SMEM128);
    cudaFuncSetAttribute(gemm_p<0, 64>,  cudaFuncAttributeMaxDynamicSharedMemorySize, GEMM_SMEM64);
    cudaFuncSetAttribute(flash_attn_tc,  cudaFuncAttributeMaxDynamicSharedMemorySize, FA_SMEM);

    // all weight transposes up front (batched over layers)
    transpose_conv<<<dim3(TD / 32, DIM / 32, NLAYER), 256>>>(c_attn_w, wqh, wql, DIM, TD);
    transpose_conv<<<dim3(DIM / 32, DIM / 32, NLAYER), 256>>>(c_proj_w, wph, wpl, DIM, DIM);
    transpose_conv<<<dim3(FD / 32, DIM / 32, NLAYER), 256>>>(c_fc_w, wfh, wfl, DIM, FD);
    transpose_conv<<<dim3(DIM / 32, FD / 32, NLAYER), 256>>>(mlp_w, wmh, wml, FD, DIM);

    embed_kernel<<<MTOK * DIM / 4 / 256, 256>>>(ids, tok_emb, pos_emb, h, hh, hl);

    for (int l = 0; l < NLAYER; l++) {
        // qkv: [4096,768] @ [768,2304] -> split bf16 (576 tiles, persistent)
        gemm_p<1, 128><<<296, 256, GEMM_SMEM128>>>(
            hh, hl, wqh + (size_t)l * TD * DIM, wql + (size_t)l * TD * DIM,
            c_attn_b + (size_t)l * TD, nullptr, nullptr, qkvh, qkvl, MTOK, TD, DIM);

        flash_attn_tc<<<dim3(SEQ / 64, BATCH * NH), 128, FA_SMEM>>>(qkvh, qkvl, ath, atl);

        // proj: [4096,768] @ [768,768] + residual h -> fp32 (384 tiles of 128x64)
        gemm_p<0, 64><<<384, 128, GEMM_SMEM64>>>(
            ath, atl, wph + (size_t)l * DIM * DIM, wpl + (size_t)l * DIM * DIM,
            c_proj_b + (size_t)l * DIM, h, a, nullptr, nullptr, MTOK, DIM, DIM);

        ln_only<<<MTOK, 256>>>(a, ln1_w + (size_t)l * DIM, ln1_b + (size_t)l * DIM,
                               n, nh, nl);

        // fc: [4096,768] @ [768,3072] + gelu -> split bf16 (768 tiles, persistent)
        gemm_p<2, 128><<<296, 256, GEMM_SMEM128>>>(
            nh, nl, wfh + (size_t)l * FD * DIM, wfl + (size_t)l * FD * DIM,
            c_fc_b + (size_t)l * FD, nullptr, nullptr, fch, fcl, MTOK, FD, DIM);

        // mlp: [4096,3072] @ [3072,768] + residual n -> fp32 (384 tiles of 128x64)
        gemm_p<0, 64><<<384, 128, GEMM_SMEM64>>>(
            fch, fcl, wmh + (size_t)l * DIM * FD, wml + (size_t)l * DIM * FD,
            mlp_b + (size_t)l * DIM, n, m, nullptr, nullptr, MTOK, DIM, FD);

        bool last = (l == NLAYER - 1);
        ln_only<<<MTOK, 256>>>(m, ln2_w + (size_t)l * DIM, ln2_b + (size_t)l * DIM,
                               last ? out : h,
                               last ? nullptr : hh, last ? nullptr : hl);
    }
}

// round 13
// speedup vs baseline: 1.0944x; 1.0152x over previous
#include <cuda_runtime.h>
#include <cuda_bf16.h>
#include <math.h>
#include <stdint.h>

#define NLAYER 5
#define BATCH 4
#define SEQ 1024
#define DIM 768
#define NH 12
#define HD 64
#define TD (3*DIM)
#define FD (4*DIM)
#define MTOK (BATCH*SEQ)   /* 4096 */

typedef __nv_bfloat16 bf16;

// ---------------- scratch (no allocations allowed) ----------------
__device__ float g_h[MTOK*DIM];
__device__ float g_a[MTOK*DIM];
__device__ float g_n[MTOK*DIM];
__device__ float g_m[MTOK*DIM];
__device__ __align__(128) bf16 g_hh[MTOK*DIM],  g_hl[MTOK*DIM];
__device__ __align__(128) bf16 g_qkvh[MTOK*TD], g_qkvl[MTOK*TD];
__device__ __align__(128) bf16 g_ath[MTOK*DIM], g_atl[MTOK*DIM];
__device__ __align__(128) bf16 g_nh[MTOK*DIM],  g_nl[MTOK*DIM];
__device__ __align__(128) bf16 g_fch[MTOK*FD],  g_fcl[MTOK*FD];
// all-layer transposed weights (hi/lo)
__device__ __align__(128) bf16 g_wqh[NLAYER*TD*DIM],  g_wql[NLAYER*TD*DIM];
__device__ __align__(128) bf16 g_wph[NLAYER*DIM*DIM], g_wpl[NLAYER*DIM*DIM];
__device__ __align__(128) bf16 g_wfh[NLAYER*FD*DIM],  g_wfl[NLAYER*FD*DIM];
__device__ __align__(128) bf16 g_wmh[NLAYER*DIM*FD],  g_wml[NLAYER*DIM*FD];

// ---------------- helpers ----------------
__device__ __forceinline__ uint32_t smem_u32(const void* p) {
    uint32_t a;
    asm("{ .reg .u64 t; cvta.to.shared.u64 t, %1; cvt.u32.u64 %0, t; }" : "=r"(a) : "l"(p));
    return a;
}

#define LDSM4(r0, r1, r2, r3, a) \
    asm volatile("ldmatrix.sync.aligned.m8n8.x4.shared.b16 {%0,%1,%2,%3}, [%4];" \
                 : "=r"(r0), "=r"(r1), "=r"(r2), "=r"(r3) : "r"(a))
#define LDSM4T(r0, r1, r2, r3, a) \
    asm volatile("ldmatrix.sync.aligned.m8n8.x4.trans.shared.b16 {%0,%1,%2,%3}, [%4];" \
                 : "=r"(r0), "=r"(r1), "=r"(r2), "=r"(r3) : "r"(a))

#define MMA16816(d, a, b) \
    asm volatile("mma.sync.aligned.m16n8k16.row.col.f32.bf16.bf16.f32 " \
                 "{%0,%1,%2,%3},{%4,%5,%6,%7},{%8,%9},{%0,%1,%2,%3};" \
                 : "+f"((d)[0]), "+f"((d)[1]), "+f"((d)[2]), "+f"((d)[3]) \
                 : "r"((a)[0]), "r"((a)[1]), "r"((a)[2]), "r"((a)[3]), \
                   "r"((b)[0]), "r"((b)[1]))

#define CP_ASYNC16(dst, src) \
    asm volatile("cp.async.cg.shared.global [%0], [%1], 16;" :: "r"(dst), "l"(src) : "memory")
#define CP_COMMIT() asm volatile("cp.async.commit_group;" ::: "memory")
#define CP_WAIT0()  asm volatile("cp.async.wait_group 0;" ::: "memory")

__device__ __forceinline__ uint32_t pk(bf16 a, bf16 b) {
    __nv_bfloat162 v(a, b);
    return *(uint32_t*)&v;
}
__device__ __forceinline__ void split2(float x0, float x1, uint32_t& hi, uint32_t& lo) {
    bf16 h0 = __float2bfloat16_rn(x0);
    bf16 h1 = __float2bfloat16_rn(x1);
    bf16 l0 = __float2bfloat16_rn(x0 - __bfloat162float(h0));
    bf16 l1 = __float2bfloat16_rn(x1 - __bfloat162float(h1));
    hi = pk(h0, h1); lo = pk(l0, l1);
}

__device__ __forceinline__ float gelu_f(float x) {
    float x3 = x * x * x;
    return 0.5f * x * (1.0f + tanhf(0.7978845608028654f * (x + 0.044715f * x3)));
}

// ---------------- embedding (fp32 + split bf16) ----------------
__global__ void embed_kernel(const int* __restrict__ ids,
                             const float* __restrict__ tok_emb,
                             const float* __restrict__ pos_emb,
                             float* __restrict__ out,
                             bf16* __restrict__ oh, bf16* __restrict__ ol) {
    int idx = blockIdx.x * blockDim.x + threadIdx.x;
    if (idx >= MTOK * DIM / 4) return;
    int d4  = idx % (DIM / 4);
    int bs  = idx / (DIM / 4);
    int s   = bs % SEQ;
    int tok = ids[bs];
    float4 t = *(const float4*)&tok_emb[(size_t)tok * DIM + d4 * 4];
    float4 p = *(const float4*)&pos_emb[(size_t)s   * DIM + d4 * 4];
    float4 o = make_float4(t.x + p.x, t.y + p.y, t.z + p.z, t.w + p.w);
    size_t off = (size_t)bs * DIM + d4 * 4;
    *(float4*)&out[off] = o;
    uint32_t h01, l01, h23, l23;
    split2(o.x, o.y, h01, l01);
    split2(o.z, o.w, h23, l23);
    *(uint32_t*)&oh[off]     = h01; *(uint32_t*)&oh[off + 2] = h23;
    *(uint32_t*)&ol[off]     = l01; *(uint32_t*)&ol[off + 2] = l23;
}

// ---------------- batched transpose + fp32 -> bf16 hi/lo split ----------------
__global__ __launch_bounds__(256)
void transpose_conv(const float* __restrict__ W,
                    bf16* __restrict__ Th, bf16* __restrict__ Tl,
                    int K, int N) {
    __shared__ float t[32][33];
    const size_t lw = (size_t)blockIdx.z * K * N;
    const float* Wl = W + lw;
    bf16* Thl = Th + lw;
    bf16* Tll = Tl + lw;
    int n0 = blockIdx.x * 32, k0 = blockIdx.y * 32;
    int tx = threadIdx.x & 31, ty = threadIdx.x >> 5;
    #pragma unroll
    for (int i = 0; i < 4; i++)
        t[ty + i * 8][tx] = Wl[(size_t)(k0 + ty + i * 8) * N + n0 + tx];
    __syncthreads();
    #pragma unroll
    for (int i = 0; i < 4; i++) {
        float v = t[tx][ty + i * 8];
        bf16 h = __float2bfloat16_rn(v);
        bf16 l = __float2bfloat16_rn(v - __bfloat162float(h));
        size_t off = (size_t)(n0 + ty + i * 8) * K + k0 + tx;
        Thl[off] = h;
        Tll[off] = l;
    }
}

// ---------------- bf16x3 tensor-core GEMM (R6 config, packed grid) ----------------
template<int NB>
__device__ __forceinline__ void load_stage(uint32_t dst,
        const bf16* A0, const bf16* A1, const bf16* B0, const bf16* B1,
        int K, int kcol, int tid) {
    if (NB == 128) {
        #pragma unroll
        for (int i = 0; i < 8; i++) {
            const int t = i >> 1;
            int g = tid + (i & 1) * 256;
            int r = g >> 2, c = g & 3;
            const bf16* src = (t == 0 ? A0 : t == 1 ? A1 : t == 2 ? B0 : B1)
                              + (size_t)r * K + kcol + c * 8;
            CP_ASYNC16(dst + t * 10240 + r * 80 + c * 16, src);
        }
    } else {  // NB==64, 128 threads
        #pragma unroll
        for (int i = 0; i < 8; i++) {
            const int sel = i >> 2;
            int g = tid + (i & 3) * 128;
            int r = g >> 2, c = g & 3;
            const bf16* src = (sel ? A1 : A0) + (size_t)r * K + kcol + c * 8;
            CP_ASYNC16(dst + sel * 10240 + r * 80 + c * 16, src);
        }
        #pragma unroll
        for (int i = 0; i < 4; i++) {
            const int sel = i >> 1;
            int g = tid + (i & 1) * 128;
            int r = g >> 2, c = g & 3;
            const bf16* src = (sel ? B1 : B0) + (size_t)r * K + kcol + c * 8;
            CP_ASYNC16(dst + 20480 + sel * (NB * 80) + r * 80 + c * 16, src);
        }
    }
}

// EPI: 0 = fp32 out + residual, 1 = split out, 2 = split out + gelu
template<int EPI, int NB>
__global__ __launch_bounds__(NB == 128 ? 256 : 128, NB == 128 ? 2 : 3)
void gemm_p(const bf16* __restrict__ Ah, const bf16* __restrict__ Al,
            const bf16* __restrict__ Bh, const bf16* __restrict__ Bl,
            const float* __restrict__ bias, const float* __restrict__ Res,
            float* __restrict__ Cf,
            bf16* __restrict__ Ch, bf16* __restrict__ Cl,
            int M, int N, int K) {
    constexpr uint32_t OAL = 10240;
    constexpr uint32_t OBH = 20480;
    constexpr uint32_t OBL = 20480 + NB * 80;
    constexpr uint32_t BUF = 20480 + 2 * NB * 80;
    extern __shared__ char dsm[];
    uint32_t sb = smem_u32(dsm);
    const int tid = threadIdx.x;
    const int lane = tid & 31, wid = tid >> 5;
    const int warp_m = wid & 1;
    const int warp_n = wid >> 1;
    const uint32_t lm_off = (uint32_t)(((lane & 7) + ((lane >> 3) & 1) * 8) * 80
                                       + ((lane >> 4) & 1) * 16);
    const int nk = K >> 5;
    const int mtiles = M >> 7;
    const int tiles = mtiles * (N / NB);

    for (int t = blockIdx.x; t < tiles; t += gridDim.x) {
        const int m0 = (t % mtiles) << 7;
        const int n0 = (t / mtiles) * NB;
        const bf16* tA0 = Ah + (size_t)m0 * K;
        const bf16* tA1 = Al + (size_t)m0 * K;
        const bf16* tB0 = Bh + (size_t)n0 * K;
        const bf16* tB1 = Bl + (size_t)n0 * K;

        load_stage<NB>(sb, tA0, tA1, tB0, tB1, K, 0, tid);
        CP_COMMIT();

        float acc[4][4][4] = {};
        for (int kc = 0; kc < nk; kc++) {
            CP_WAIT0();
            __syncthreads();
            if (kc + 1 < nk) {
                load_stage<NB>(sb + ((kc + 1) & 1) * BUF, tA0, tA1, tB0, tB1,
                               K, (kc + 1) * 32, tid);
                CP_COMMIT();
            }
            const uint32_t sA = sb + (uint32_t)((kc & 1) * BUF);
            #pragma unroll
            for (int ks = 0; ks < 2; ks++) {
                uint32_t ah[4][4], al[4][4], bh[4][2], bl[4][2];
                // pass 1: Ah x Bh
                #pragma unroll
                for (int mt = 0; mt < 4; mt++) {
                    uint32_t ad = sA + (uint32_t)((warp_m * 64 + mt * 16) * 80 + ks * 32) + lm_off;
                    LDSM4(ah[mt][0], ah[mt][1], ah[mt][2], ah[mt][3], ad);
                }
                #pragma unroll
                for (int ntp = 0; ntp < 2; ntp++) {
                    uint32_t bd = sA + OBH +
                                  (uint32_t)((warp_n * 32 + ntp * 16) * 80 + ks * 32) + lm_off;
                    uint32_t r0, r1, r2, r3;
                    LDSM4(r0, r1, r2, r3, bd);
                    bh[2 * ntp][0] = r0; bh[2 * ntp][1] = r2;
                    bh[2 * ntp + 1][0] = r1; bh[2 * ntp + 1][1] = r3;
                }
                #pragma unroll
                for (int mt = 0; mt < 4; mt++)
                    #pragma unroll
                    for (int nt = 0; nt < 4; nt++)
                        MMA16816(acc[mt][nt], ah[mt], bh[nt]);
                // pass 2: Ah x Bl
                #pragma unroll
                for (int ntp = 0; ntp < 2; ntp++) {
                    uint32_t bd = sA + OBL +
                                  (uint32_t)((warp_n * 32 + ntp * 16) * 80 + ks * 32) + lm_off;
                    uint32_t r0, r1, r2, r3;
                    LDSM4(r0, r1, r2, r3, bd);
                    bl[2 * ntp][0] = r0; bl[2 * ntp][1] = r2;
                    bl[2 * ntp + 1][0] = r1; bl[2 * ntp + 1][1] = r3;
                }
                #pragma unroll
                for (int mt = 0; mt < 4; mt++)
                    #pragma unroll
                    for (int nt = 0; nt < 4; nt++)
                        MMA16816(acc[mt][nt], ah[mt], bl[nt]);
                // pass 3: Al x Bh
                #pragma unroll
                for (int mt = 0; mt < 4; mt++) {
                    uint32_t ad = sA + OAL +
                                  (uint32_t)((warp_m * 64 + mt * 16) * 80 + ks * 32) + lm_off;
                    LDSM4(al[mt][0], al[mt][1], al[mt][2], al[mt][3], ad);
                }
                #pragma unroll
                for (int mt = 0; mt < 4; mt++)
                    #pragma unroll
                    for (int nt = 0; nt < 4; nt++)
                        MMA16816(acc[mt][nt], al[mt], bh[nt]);
            }
        }

        // epilogue
        #pragma unroll
        for (int mt = 0; mt < 4; mt++) {
            int r = m0 + warp_m * 64 + mt * 16 + (lane >> 2);
            #pragma unroll
            for (int nt = 0; nt < 4; nt++) {
                int ccol = n0 + warp_n * 32 + nt * 8 + (lane & 3) * 2;
                float2 bb = *(const float2*)&bias[ccol];
                float x0 = acc[mt][nt][0] + bb.x;
                float x1 = acc[mt][nt][1] + bb.y;
                float x2 = acc[mt][nt][2] + bb.x;
                float x3 = acc[mt][nt][3] + bb.y;
                if (EPI == 2) { x0 = gelu_f(x0); x1 = gelu_f(x1); x2 = gelu_f(x2); x3 = gelu_f(x3); }
                if (EPI == 0) {
                    // fused residual add
                    float2 r0 = *(const float2*)&Res[(size_t)r * N + ccol];
                    float2 r1 = *(const float2*)&Res[(size_t)(r + 8) * N + ccol];
                    *(float2*)&Cf[(size_t)r * N + ccol] =
                        make_float2(x0 + r0.x, x1 + r0.y);
                    *(float2*)&Cf[(size_t)(r + 8) * N + ccol] =
                        make_float2(x2 + r1.x, x3 + r1.y);
                } else {
                    uint32_t hi, lo;
                    split2(x0, x1, hi, lo);
                    *(uint32_t*)&Ch[(size_t)r * N + ccol] = hi;
                    *(uint32_t*)&Cl[(size_t)r * N + ccol] = lo;
                    split2(x2, x3, hi, lo);
                    *(uint32_t*)&Ch[(size_t)(r + 8) * N + ccol] = hi;
                    *(uint32_t*)&Cl[(size_t)(r + 8) * N + ccol] = lo;
                }
            }
        }
    }
}

#define GEMM_SMEM128 (2 * (20480 + 2 * 128 * 80))
#define GEMM_SMEM64  (2 * (20480 + 2 * 64 * 80))

// ---------------- tensor-core causal flash attention (bf16x3, BM=64, R6) ----------------
#define FA_STRIDE 144
#define FA_QTILE  9216
#define FA_STAGE  (4 * FA_QTILE)
#define FA_SMEM   (2 * FA_QTILE + 2 * FA_STAGE)

__device__ __forceinline__ void fa_load_kv(uint32_t dst,
                                           const bf16* qh_, const bf16* ql_,
                                           size_t kbase, int tid) {
    #pragma unroll
    for (int i = 0; i < 16; i++) {
        const int t = i >> 2;
        int g = tid + (i & 3) * 128;
        int r = g >> 3, c = g & 7;
        const bf16* base = (t & 1) ? ql_ : qh_;
        const bf16* src = base + kbase + ((t >> 1) ? (size_t)DIM : (size_t)0)
                          + (size_t)r * TD + c * 8;
        CP_ASYNC16(dst + t * FA_QTILE + r * FA_STRIDE + c * 16, src);
    }
}

__global__ __launch_bounds__(128)
void flash_attn_tc(const bf16* __restrict__ qh_, const bf16* __restrict__ ql_,
                   bf16* __restrict__ oh_, bf16* __restrict__ ol_) {
    extern __shared__ char dsm[];
    uint32_t sb = smem_u32(dsm);
    const int qb = gridDim.x - 1 - blockIdx.x;
    const int bh = blockIdx.y;
    const int b = bh / NH, hh = bh % NH;
    const int tid = threadIdx.x, lane = tid & 31, w = tid >> 5;
    const int wrow = w * 16;

    {
        size_t qrow0 = ((size_t)(b * SEQ + qb * 64)) * TD + hh * HD;
        #pragma unroll
        for (int i = 0; i < 8; i++) {
            const int t = i >> 2;
            int g = tid + (i & 3) * 128;
            int r = g >> 3, c = g & 7;
            const bf16* src = (t ? ql_ : qh_) + qrow0 + (size_t)r * TD + c * 8;
            CP_ASYNC16(sb + t * FA_QTILE + r * FA_STRIDE + c * 16, src);
        }
    }
    fa_load_kv(sb + 2 * FA_QTILE, qh_, ql_,
               ((size_t)(b * SEQ)) * TD + DIM + hh * HD, tid);
    CP_COMMIT();

    const uint32_t lmA = sb + (uint32_t)((wrow + (lane & 7) + ((lane >> 3) & 1) * 8) * FA_STRIDE
                                         + ((lane >> 4) & 1) * 16);
    const uint32_t lmB = (uint32_t)((lane & 15) * FA_STRIDE + ((lane >> 4) & 1) * 16);
    const uint32_t lmV = lmB;

    float oacc[8][4] = {};
    float mi[2] = { -1e30f, -1e30f };
    float li[2] = { 0.0f, 0.0f };

    for (int kt = 0; kt <= qb; kt++) {
        CP_WAIT0();
        __syncthreads();
        if (kt < qb) {
            fa_load_kv(sb + 2 * FA_QTILE + ((kt + 1) & 1) * FA_STAGE, qh_, ql_,
                       ((size_t)(b * SEQ + (kt + 1) * 64)) * TD + DIM + hh * HD, tid);
            CP_COMMIT();
        }
        const uint32_t stg = sb + 2 * FA_QTILE + (uint32_t)((kt & 1) * FA_STAGE);
        const uint32_t sK = stg, sV = stg + 2 * FA_QTILE;

        float sacc[8][4] = {};
        #pragma unroll
        for (int ks = 0; ks < 4; ks++) {
            uint32_t qhf[4], qlf[4];
            LDSM4(qhf[0], qhf[1], qhf[2], qhf[3], lmA + ks * 32);
            LDSM4(qlf[0], qlf[1], qlf[2], qlf[3], lmA + FA_QTILE + ks * 32);
            #pragma unroll
            for (int jp = 0; jp < 4; jp++) {
                uint32_t r0, r1, r2, r3;
                uint32_t bh0[2], bh1[2], bl0[2], bl1[2];
                uint32_t kb = sK + (uint32_t)(jp * 16 * FA_STRIDE) + lmB + ks * 32;
                LDSM4(r0, r1, r2, r3, kb);
                bh0[0] = r0; bh0[1] = r2; bh1[0] = r1; bh1[1] = r3;
                LDSM4(r0, r1, r2, r3, kb + FA_QTILE);
                bl0[0] = r0; bl0[1] = r2; bl1[0] = r1; bl1[1] = r3;
                MMA16816(sacc[2 * jp],     qhf, bh0);
                MMA16816(sacc[2 * jp],     qhf, bl0);
                MMA16816(sacc[2 * jp],     qlf, bh0);
                MMA16816(sacc[2 * jp + 1], qhf, bh1);
                MMA16816(sacc[2 * jp + 1], qhf, bl1);
                MMA16816(sacc[2 * jp + 1], qlf, bh1);
            }
        }

        if (kt == qb) {
            #pragma unroll
            for (int nt = 0; nt < 8; nt++)
                #pragma unroll
                for (int e = 0; e < 4; e++) {
                    int jl = nt * 8 + (lane & 3) * 2 + (e & 1);
                    int il = wrow + (lane >> 2) + (e >> 1) * 8;
                    float s = sacc[nt][e];
                    sacc[nt][e] = (jl <= il) ? s * 0.125f : -1e4f;
                }
        } else {
            #pragma unroll
            for (int nt = 0; nt < 8; nt++)
                #pragma unroll
                for (int e = 0; e < 4; e++)
                    sacc[nt][e] *= 0.125f;
        }

        #pragma unroll
        for (int hf = 0; hf < 2; hf++) {
            const int e0 = hf * 2;
            float mx = -1e30f;
            #pragma unroll
            for (int nt = 0; nt < 8; nt++)
                mx = fmaxf(mx, fmaxf(sacc[nt][e0], sacc[nt][e0 + 1]));
            mx = fmaxf(mx, __shfl_xor_sync(0xffffffffu, mx, 1));
            mx = fmaxf(mx, __shfl_xor_sync(0xffffffffu, mx, 2));
            float mn = fmaxf(mi[hf], mx);
            float alpha = __expf(mi[hf] - mn);
            float sum = 0.0f;
            #pragma unroll
            for (int nt = 0; nt < 8; nt++) {
                float p0 = __expf(sacc[nt][e0] - mn);
                float p1 = __expf(sacc[nt][e0 + 1] - mn);
                sacc[nt][e0] = p0; sacc[nt][e0 + 1] = p1;
                sum += p0 + p1;
            }
            sum += __shfl_xor_sync(0xffffffffu, sum, 1);
            sum += __shfl_xor_sync(0xffffffffu, sum, 2);
            li[hf] = li[hf] * alpha + sum;
            mi[hf] = mn;
            #pragma unroll
            for (int nt = 0; nt < 8; nt++) {
                oacc[nt][e0]     *= alpha;
                oacc[nt][e0 + 1] *= alpha;
            }
        }

        #pragma unroll
        for (int kk = 0; kk < 4; kk++) {
            uint32_t ph[4], pl[4];
            split2(sacc[2 * kk][0],     sacc[2 * kk][1],     ph[0], pl[0]);
            split2(sacc[2 * kk][2],     sacc[2 * kk][3],     ph[1], pl[1]);
            split2(sacc[2 * kk + 1][0], sacc[2 * kk + 1][1], ph[2], pl[2]);
            split2(sacc[2 * kk + 1][2], sacc[2 * kk + 1][3], ph[3], pl[3]);
            #pragma unroll
            for (int dp = 0; dp < 4; dp++) {
                uint32_t h0, h1, h2, h3, l0, l1, l2, l3;
                uint32_t vb = sV + (uint32_t)(kk * 16 * FA_STRIDE + dp * 32) + lmV;
                LDSM4T(h0, h1, h2, h3, vb);
                LDSM4T(l0, l1, l2, l3, vb + FA_QTILE);
                uint32_t vh0[2] = { h0, h1 }, vh1[2] = { h2, h3 };
                uint32_t vl0[2] = { l0, l1 }, vl1[2] = { l2, l3 };
                MMA16816(oacc[2 * dp],     ph, vh0);
                MMA16816(oacc[2 * dp],     ph, vl0);
                MMA16816(oacc[2 * dp],     pl, vh0);
                MMA16816(oacc[2 * dp + 1], ph, vh1);
                MMA16816(oacc[2 * dp + 1], ph, vl1);
                MMA16816(oacc[2 * dp + 1], pl, vh1);
            }
        }
    }

    const float inv0 = 1.0f / li[0], inv1 = 1.0f / li[1];
    const int i0 = qb * 64 + wrow + (lane >> 2);
    const size_t row0 = ((size_t)(b * SEQ) + i0) * DIM + hh * HD;
    const size_t row1 = row0 + (size_t)8 * DIM;
    #pragma unroll
    for (int nt = 0; nt < 8; nt++) {
        int d = nt * 8 + (lane & 3) * 2;
        uint32_t hi, lo;
        split2(oacc[nt][0] * inv0, oacc[nt][1] * inv0, hi, lo);
        *(uint32_t*)&oh_[row0 + d] = hi;
        *(uint32_t*)&ol_[row0 + d] = lo;
        split2(oacc[nt][2] * inv1, oacc[nt][3] * inv1, hi, lo);
        *(uint32_t*)&oh_[row1 + d] = hi;
        *(uint32_t*)&ol_[row1 + d] = lo;
    }
}

// ---------------- layernorm on pre-summed input (+ optional split) ----------------
__global__ __launch_bounds__(256)
void ln_only(const float* __restrict__ x,
             const float* __restrict__ w, const float* __restrict__ bvec,
             float* __restrict__ out,
             bf16* __restrict__ oh, bf16* __restrict__ ol) {
    int row = blockIdx.x;
    int tid = threadIdx.x;
    const float* xr = x + (size_t)row * DIM;
    float v[3];
    float s = 0.0f;
    #pragma unroll
    for (int i = 0; i < 3; i++) {
        int c = tid + i * 256;
        v[i] = xr[c];
        s += v[i];
    }
    __shared__ float red[8];
    #pragma unroll
    for (int o = 16; o; o >>= 1) s += __shfl_xor_sync(0xffffffffu, s, o);
    if ((tid & 31) == 0) red[tid >> 5] = s;
    __syncthreads();
    float tot = 0.0f;
    #pragma unroll
    for (int i = 0; i < 8; i++) tot += red[i];
    float mu = tot * (1.0f / DIM);

    float s2 = 0.0f;
    #pragma unroll
    for (int i = 0; i < 3; i++) {
        float d = v[i] - mu;
        s2 += d * d;
    }
    __syncthreads();
    #pragma unroll
    for (int o = 16; o; o >>= 1) s2 += __shfl_xor_sync(0xffffffffu, s2, o);
    if ((tid & 31) == 0) red[tid >> 5] = s2;
    __syncthreads();
    float tot2 = 0.0f;
    #pragma unroll
    for (int i = 0; i < 8; i++) tot2 += red[i];
    float rinv = rsqrtf(tot2 * (1.0f / DIM) + 1e-5f);

    #pragma unroll
    for (int i = 0; i < 3; i++) {
        int c = tid + i * 256;
        float val = (v[i] - mu) * rinv * w[c] + bvec[c];
        size_t off = (size_t)row * DIM + c;
        out[off] = val;
        if (oh) {
            bf16 h = __float2bfloat16_rn(val);
            oh[off] = h;
            ol[off] = __float2bfloat16_rn(val - __bfloat162float(h));
        }
    }
}

// ---------------- launch ----------------
extern "C" void kernel_launch(void* const* d_in, const int* in_sizes, int n_in,
                              void* d_out, int out_size) {
    (void)in_sizes; (void)n_in; (void)out_size;
    const int*   ids      = (const int*)  d_in[0];
    const float* tok_emb  = (const float*)d_in[3];
    const float* pos_emb  = (const float*)d_in[4];
    const float* c_attn_w = (const float*)d_in[5];
    const float* c_attn_b = (const float*)d_in[6];
    const float* c_proj_w = (const float*)d_in[7];
    const float* c_proj_b = (const float*)d_in[8];
    const float* ln1_w    = (const float*)d_in[9];
    const float* ln1_b    = (const float*)d_in[10];
    const float* c_fc_w   = (const float*)d_in[11];
    const float* c_fc_b   = (const float*)d_in[12];
    const float* mlp_w    = (const float*)d_in[13];
    const float* mlp_b    = (const float*)d_in[14];
    const float* ln2_w    = (const float*)d_in[15];
    const float* ln2_b    = (const float*)d_in[16];
    float* out = (float*)d_out;

    float *h, *a, *n, *m;
    bf16 *hh, *hl, *qkvh, *qkvl, *ath, *atl, *nh, *nl, *fch, *fcl;
    bf16 *wqh, *wql, *wph, *wpl, *wfh, *wfl, *wmh, *wml;
    cudaGetSymbolAddress((void**)&h,    g_h);
    cudaGetSymbolAddress((void**)&a,    g_a);
    cudaGetSymbolAddress((void**)&n,    g_n);
    cudaGetSymbolAddress((void**)&m,    g_m);
    cudaGetSymbolAddress((void**)&hh,   g_hh);
    cudaGetSymbolAddress((void**)&hl,   g_hl);
    cudaGetSymbolAddress((void**)&qkvh, g_qkvh);
    cudaGetSymbolAddress((void**)&qkvl, g_qkvl);
    cudaGetSymbolAddress((void**)&ath,  g_ath);
    cudaGetSymbolAddress((void**)&atl,  g_atl);
    cudaGetSymbolAddress((void**)&nh,   g_nh);
    cudaGetSymbolAddress((void**)&nl,   g_nl);
    cudaGetSymbolAddress((void**)&fch,  g_fch);
    cudaGetSymbolAddress((void**)&fcl,  g_fcl);
    cudaGetSymbolAddress((void**)&wqh,  g_wqh);
    cudaGetSymbolAddress((void**)&wql,  g_wql);
    cudaGetSymbolAddress((void**)&wph,  g_wph);
    cudaGetSymbolAddress((void**)&wpl,  g_wpl);
    cudaGetSymbolAddress((void**)&wfh,  g_wfh);
    cudaGetSymbolAddress((void**)&wfl,  g_wfl);
    cudaGetSymbolAddress((void**)&wmh,  g_wmh);
    cudaGetSymbolAddress((void**)&wml,  g_wml);

    cudaFuncSetAttribute(gemm_p<1, 128>, cudaFuncAttributeMaxDynamicSharedMemorySize, GEMM_SMEM128);
    cudaFuncSetAttribute(gemm_p<2, 128>, cudaFuncAttributeMaxDynamicSharedMemorySize, GEMM_SMEM128);
    cudaFuncSetAttribute(gemm_p<0, 64>,  cudaFuncAttributeMaxDynamicSharedMemorySize, GEMM_SMEM64);
    cudaFuncSetAttribute(flash_attn_tc,  cudaFuncAttributeMaxDynamicSharedMemorySize, FA_SMEM);

    // all weight transposes up front (batched over layers)
    transpose_conv<<<dim3(TD / 32, DIM / 32, NLAYER), 256>>>(c_attn_w, wqh, wql, DIM, TD);
    transpose_conv<<<dim3(DIM / 32, DIM / 32, NLAYER), 256>>>(c_proj_w, wph, wpl, DIM, DIM);
    transpose_conv<<<dim3(FD / 32, DIM / 32, NLAYER), 256>>>(c_fc_w, wfh, wfl, DIM, FD);
    transpose_conv<<<dim3(DIM / 32, FD / 32, NLAYER), 256>>>(mlp_w, wmh, wml, FD, DIM);

    embed_kernel<<<MTOK * DIM / 4 / 256, 256>>>(ids, tok_emb, pos_emb, h, hh, hl);

    for (int l = 0; l < NLAYER; l++) {
        // qkv: [4096,768] @ [768,2304] -> split bf16 (576 tiles, packed grid)
        gemm_p<1, 128><<<576, 256, GEMM_SMEM128>>>(
            hh, hl, wqh + (size_t)l * TD * DIM, wql + (size_t)l * TD * DIM,
            c_attn_b + (size_t)l * TD, nullptr, nullptr, qkvh, qkvl, MTOK, TD, DIM);

        flash_attn_tc<<<dim3(SEQ / 64, BATCH * NH), 128, FA_SMEM>>>(qkvh, qkvl, ath, atl);

        // proj: [4096,768] @ [768,768] + residual h -> fp32 (384 tiles of 128x64)
        gemm_p<0, 64><<<384, 128, GEMM_SMEM64>>>(
            ath, atl, wph + (size_t)l * DIM * DIM, wpl + (size_t)l * DIM * DIM,
            c_proj_b + (size_t)l * DIM, h, a, nullptr, nullptr, MTOK, DIM, DIM);

        ln_only<<<MTOK, 256>>>(a, ln1_w + (size_t)l * DIM, ln1_b + (size_t)l * DIM,
                               n, nh, nl);

        // fc: [4096,768] @ [768,3072] + gelu -> split bf16 (768 tiles, packed grid)
        gemm_p<2, 128><<<768, 256, GEMM_SMEM128>>>(
            nh, nl, wfh + (size_t)l * FD * DIM, wfl + (size_t)l * FD * DIM,
            c_fc_b + (size_t)l * FD, nullptr, nullptr, fch, fcl, MTOK, FD, DIM);

        // mlp: [4096,3072] @ [3072,768] + residual n -> fp32 (384 tiles of 128x64)
        gemm_p<0, 64><<<384, 128, GEMM_SMEM64>>>(
            fch, fcl, wmh + (size_t)l * DIM * FD, wml + (size_t)l * DIM * FD,
            mlp_b + (size_t)l * DIM, n, m, nullptr, nullptr, MTOK, DIM, FD);

        bool last = (l == NLAYER - 1);
        ln_only<<<MTOK, 256>>>(m, ln2_w + (size_t)l * DIM, ln2_b + (size_t)l * DIM,
                               last ? out : h,
                               last ? nullptr : hh, last ? nullptr : hl);
    }
}

// round 14
// speedup vs baseline: 1.1002x; 1.0053x over previous
#include <cuda_runtime.h>
#include <cuda_bf16.h>
#include <math.h>
#include <stdint.h>

#define NLAYER 5
#define BATCH 4
#define SEQ 1024
#define DIM 768
#define NH 12
#define HD 64
#define TD (3*DIM)
#define FD (4*DIM)
#define MTOK (BATCH*SEQ)   /* 4096 */

typedef __nv_bfloat16 bf16;

// ---------------- scratch (no allocations allowed) ----------------
__device__ float g_h[MTOK*DIM];
__device__ float g_a[MTOK*DIM];
__device__ float g_n[MTOK*DIM];
__device__ float g_m[MTOK*DIM];
__device__ __align__(128) bf16 g_hh[MTOK*DIM],  g_hl[MTOK*DIM];
__device__ __align__(128) bf16 g_qkvh[MTOK*TD], g_qkvl[MTOK*TD];
__device__ __align__(128) bf16 g_ath[MTOK*DIM], g_atl[MTOK*DIM];
__device__ __align__(128) bf16 g_nh[MTOK*DIM],  g_nl[MTOK*DIM];
__device__ __align__(128) bf16 g_fch[MTOK*FD],  g_fcl[MTOK*FD];
// all-layer transposed weights (hi/lo)
__device__ __align__(128) bf16 g_wqh[NLAYER*TD*DIM],  g_wql[NLAYER*TD*DIM];
__device__ __align__(128) bf16 g_wph[NLAYER*DIM*DIM], g_wpl[NLAYER*DIM*DIM];
__device__ __align__(128) bf16 g_wfh[NLAYER*FD*DIM],  g_wfl[NLAYER*FD*DIM];
__device__ __align__(128) bf16 g_wmh[NLAYER*DIM*FD],  g_wml[NLAYER*DIM*FD];

// ---------------- helpers ----------------
__device__ __forceinline__ uint32_t smem_u32(const void* p) {
    uint32_t a;
    asm("{ .reg .u64 t; cvta.to.shared.u64 t, %1; cvt.u32.u64 %0, t; }" : "=r"(a) : "l"(p));
    return a;
}

#define LDSM4(r0, r1, r2, r3, a) \
    asm volatile("ldmatrix.sync.aligned.m8n8.x4.shared.b16 {%0,%1,%2,%3}, [%4];" \
                 : "=r"(r0), "=r"(r1), "=r"(r2), "=r"(r3) : "r"(a))
#define LDSM4T(r0, r1, r2, r3, a) \
    asm volatile("ldmatrix.sync.aligned.m8n8.x4.trans.shared.b16 {%0,%1,%2,%3}, [%4];" \
                 : "=r"(r0), "=r"(r1), "=r"(r2), "=r"(r3) : "r"(a))

#define MMA16816(d, a, b) \
    asm volatile("mma.sync.aligned.m16n8k16.row.col.f32.bf16.bf16.f32 " \
                 "{%0,%1,%2,%3},{%4,%5,%6,%7},{%8,%9},{%0,%1,%2,%3};" \
                 : "+f"((d)[0]), "+f"((d)[1]), "+f"((d)[2]), "+f"((d)[3]) \
                 : "r"((a)[0]), "r"((a)[1]), "r"((a)[2]), "r"((a)[3]), \
                   "r"((b)[0]), "r"((b)[1]))

#define CP_ASYNC16(dst, src) \
    asm volatile("cp.async.cg.shared.global [%0], [%1], 16;" :: "r"(dst), "l"(src) : "memory")
#define CP_COMMIT() asm volatile("cp.async.commit_group;" ::: "memory")
#define CP_WAIT0()  asm volatile("cp.async.wait_group 0;" ::: "memory")

__device__ __forceinline__ uint32_t pk(bf16 a, bf16 b) {
    __nv_bfloat162 v(a, b);
    return *(uint32_t*)&v;
}
__device__ __forceinline__ void split2(float x0, float x1, uint32_t& hi, uint32_t& lo) {
    bf16 h0 = __float2bfloat16_rn(x0);
    bf16 h1 = __float2bfloat16_rn(x1);
    bf16 l0 = __float2bfloat16_rn(x0 - __bfloat162float(h0));
    bf16 l1 = __float2bfloat16_rn(x1 - __bfloat162float(h1));
    hi = pk(h0, h1); lo = pk(l0, l1);
}

__device__ __forceinline__ float gelu_f(float x) {
    float x3 = x * x * x;
    return 0.5f * x * (1.0f + tanhf(0.7978845608028654f * (x + 0.044715f * x3)));
}

// ---------------- embedding (fp32 + split bf16) ----------------
__global__ void embed_kernel(const int* __restrict__ ids,
                             const float* __restrict__ tok_emb,
                             const float* __restrict__ pos_emb,
                             float* __restrict__ out,
                             bf16* __restrict__ oh, bf16* __restrict__ ol) {
    int idx = blockIdx.x * blockDim.x + threadIdx.x;
    if (idx >= MTOK * DIM / 4) return;
    int d4  = idx % (DIM / 4);
    int bs  = idx / (DIM / 4);
    int s   = bs % SEQ;
    int tok = ids[bs];
    float4 t = *(const float4*)&tok_emb[(size_t)tok * DIM + d4 * 4];
    float4 p = *(const float4*)&pos_emb[(size_t)s   * DIM + d4 * 4];
    float4 o = make_float4(t.x + p.x, t.y + p.y, t.z + p.z, t.w + p.w);
    size_t off = (size_t)bs * DIM + d4 * 4;
    *(float4*)&out[off] = o;
    uint32_t h01, l01, h23, l23;
    split2(o.x, o.y, h01, l01);
    split2(o.z, o.w, h23, l23);
    *(uint2*)&oh[off] = make_uint2(h01, h23);
    *(uint2*)&ol[off] = make_uint2(l01, l23);
}

// ---------------- batched transpose + fp32 -> bf16 hi/lo split ----------------
__global__ __launch_bounds__(256)
void transpose_conv(const float* __restrict__ W,
                    bf16* __restrict__ Th, bf16* __restrict__ Tl,
                    int K, int N) {
    __shared__ float t[32][33];
    const size_t lw = (size_t)blockIdx.z * K * N;
    const float* Wl = W + lw;
    bf16* Thl = Th + lw;
    bf16* Tll = Tl + lw;
    int n0 = blockIdx.x * 32, k0 = blockIdx.y * 32;
    int tx = threadIdx.x & 31, ty = threadIdx.x >> 5;
    #pragma unroll
    for (int i = 0; i < 4; i++)
        t[ty + i * 8][tx] = Wl[(size_t)(k0 + ty + i * 8) * N + n0 + tx];
    __syncthreads();
    #pragma unroll
    for (int i = 0; i < 4; i++) {
        float v = t[tx][ty + i * 8];
        bf16 h = __float2bfloat16_rn(v);
        bf16 l = __float2bfloat16_rn(v - __bfloat162float(h));
        size_t off = (size_t)(n0 + ty + i * 8) * K + k0 + tx;
        Thl[off] = h;
        Tll[off] = l;
    }
}

// ---------------- bf16x3 tensor-core GEMM (R6 config, packed grid) ----------------
template<int NB>
__device__ __forceinline__ void load_stage(uint32_t dst,
        const bf16* A0, const bf16* A1, const bf16* B0, const bf16* B1,
        int K, int kcol, int tid) {
    if (NB == 128) {
        #pragma unroll
        for (int i = 0; i < 8; i++) {
            const int t = i >> 1;
            int g = tid + (i & 1) * 256;
            int r = g >> 2, c = g & 3;
            const bf16* src = (t == 0 ? A0 : t == 1 ? A1 : t == 2 ? B0 : B1)
                              + (size_t)r * K + kcol + c * 8;
            CP_ASYNC16(dst + t * 10240 + r * 80 + c * 16, src);
        }
    } else {  // NB==64, 128 threads
        #pragma unroll
        for (int i = 0; i < 8; i++) {
            const int sel = i >> 2;
            int g = tid + (i & 3) * 128;
            int r = g >> 2, c = g & 3;
            const bf16* src = (sel ? A1 : A0) + (size_t)r * K + kcol + c * 8;
            CP_ASYNC16(dst + sel * 10240 + r * 80 + c * 16, src);
        }
        #pragma unroll
        for (int i = 0; i < 4; i++) {
            const int sel = i >> 1;
            int g = tid + (i & 1) * 128;
            int r = g >> 2, c = g & 3;
            const bf16* src = (sel ? B1 : B0) + (size_t)r * K + kcol + c * 8;
            CP_ASYNC16(dst + 20480 + sel * (NB * 80) + r * 80 + c * 16, src);
        }
    }
}

// EPI: 0 = fp32 out + residual, 1 = split out, 2 = split out + gelu
template<int EPI, int NB>
__global__ __launch_bounds__(NB == 128 ? 256 : 128, NB == 128 ? 2 : 3)
void gemm_p(const bf16* __restrict__ Ah, const bf16* __restrict__ Al,
            const bf16* __restrict__ Bh, const bf16* __restrict__ Bl,
            const float* __restrict__ bias, const float* __restrict__ Res,
            float* __restrict__ Cf,
            bf16* __restrict__ Ch, bf16* __restrict__ Cl,
            int M, int N, int K) {
    constexpr uint32_t OAL = 10240;
    constexpr uint32_t OBH = 20480;
    constexpr uint32_t OBL = 20480 + NB * 80;
    constexpr uint32_t BUF = 20480 + 2 * NB * 80;
    extern __shared__ char dsm[];
    uint32_t sb = smem_u32(dsm);
    const int tid = threadIdx.x;
    const int lane = tid & 31, wid = tid >> 5;
    const int warp_m = wid & 1;
    const int warp_n = wid >> 1;
    const uint32_t lm_off = (uint32_t)(((lane & 7) + ((lane >> 3) & 1) * 8) * 80
                                       + ((lane >> 4) & 1) * 16);
    const int nk = K >> 5;
    const int mtiles = M >> 7;
    const int tiles = mtiles * (N / NB);

    for (int t = blockIdx.x; t < tiles; t += gridDim.x) {
        const int m0 = (t % mtiles) << 7;
        const int n0 = (t / mtiles) * NB;
        const bf16* tA0 = Ah + (size_t)m0 * K;
        const bf16* tA1 = Al + (size_t)m0 * K;
        const bf16* tB0 = Bh + (size_t)n0 * K;
        const bf16* tB1 = Bl + (size_t)n0 * K;

        load_stage<NB>(sb, tA0, tA1, tB0, tB1, K, 0, tid);
        CP_COMMIT();

        float acc[4][4][4] = {};
        for (int kc = 0; kc < nk; kc++) {
            CP_WAIT0();
            __syncthreads();
            if (kc + 1 < nk) {
                load_stage<NB>(sb + ((kc + 1) & 1) * BUF, tA0, tA1, tB0, tB1,
                               K, (kc + 1) * 32, tid);
                CP_COMMIT();
            }
            const uint32_t sA = sb + (uint32_t)((kc & 1) * BUF);
            #pragma unroll
            for (int ks = 0; ks < 2; ks++) {
                uint32_t ah[4][4], al[4][4], bh[4][2], bl[4][2];
                // pass 1: Ah x Bh
                #pragma unroll
                for (int mt = 0; mt < 4; mt++) {
                    uint32_t ad = sA + (uint32_t)((warp_m * 64 + mt * 16) * 80 + ks * 32) + lm_off;
                    LDSM4(ah[mt][0], ah[mt][1], ah[mt][2], ah[mt][3], ad);
                }
                #pragma unroll
                for (int ntp = 0; ntp < 2; ntp++) {
                    uint32_t bd = sA + OBH +
                                  (uint32_t)((warp_n * 32 + ntp * 16) * 80 + ks * 32) + lm_off;
                    uint32_t r0, r1, r2, r3;
                    LDSM4(r0, r1, r2, r3, bd);
                    bh[2 * ntp][0] = r0; bh[2 * ntp][1] = r2;
                    bh[2 * ntp + 1][0] = r1; bh[2 * ntp + 1][1] = r3;
                }
                #pragma unroll
                for (int mt = 0; mt < 4; mt++)
                    #pragma unroll
                    for (int nt = 0; nt < 4; nt++)
                        MMA16816(acc[mt][nt], ah[mt], bh[nt]);
                // pass 2: Ah x Bl
                #pragma unroll
                for (int ntp = 0; ntp < 2; ntp++) {
                    uint32_t bd = sA + OBL +
                                  (uint32_t)((warp_n * 32 + ntp * 16) * 80 + ks * 32) + lm_off;
                    uint32_t r0, r1, r2, r3;
                    LDSM4(r0, r1, r2, r3, bd);
                    bl[2 * ntp][0] = r0; bl[2 * ntp][1] = r2;
                    bl[2 * ntp + 1][0] = r1; bl[2 * ntp + 1][1] = r3;
                }
                #pragma unroll
                for (int mt = 0; mt < 4; mt++)
                    #pragma unroll
                    for (int nt = 0; nt < 4; nt++)
                        MMA16816(acc[mt][nt], ah[mt], bl[nt]);
                // pass 3: Al x Bh
                #pragma unroll
                for (int mt = 0; mt < 4; mt++) {
                    uint32_t ad = sA + OAL +
                                  (uint32_t)((warp_m * 64 + mt * 16) * 80 + ks * 32) + lm_off;
                    LDSM4(al[mt][0], al[mt][1], al[mt][2], al[mt][3], ad);
                }
                #pragma unroll
                for (int mt = 0; mt < 4; mt++)
                    #pragma unroll
                    for (int nt = 0; nt < 4; nt++)
                        MMA16816(acc[mt][nt], al[mt], bh[nt]);
            }
        }

        // epilogue
        #pragma unroll
        for (int mt = 0; mt < 4; mt++) {
            int r = m0 + warp_m * 64 + mt * 16 + (lane >> 2);
            #pragma unroll
            for (int nt = 0; nt < 4; nt++) {
                int ccol = n0 + warp_n * 32 + nt * 8 + (lane & 3) * 2;
                float2 bb = *(const float2*)&bias[ccol];
                float x0 = acc[mt][nt][0] + bb.x;
                float x1 = acc[mt][nt][1] + bb.y;
                float x2 = acc[mt][nt][2] + bb.x;
                float x3 = acc[mt][nt][3] + bb.y;
                if (EPI == 2) { x0 = gelu_f(x0); x1 = gelu_f(x1); x2 = gelu_f(x2); x3 = gelu_f(x3); }
                if (EPI == 0) {
                    // fused residual add
                    float2 r0 = *(const float2*)&Res[(size_t)r * N + ccol];
                    float2 r1 = *(const float2*)&Res[(size_t)(r + 8) * N + ccol];
                    *(float2*)&Cf[(size_t)r * N + ccol] =
                        make_float2(x0 + r0.x, x1 + r0.y);
                    *(float2*)&Cf[(size_t)(r + 8) * N + ccol] =
                        make_float2(x2 + r1.x, x3 + r1.y);
                } else {
                    uint32_t hi, lo;
                    split2(x0, x1, hi, lo);
                    *(uint32_t*)&Ch[(size_t)r * N + ccol] = hi;
                    *(uint32_t*)&Cl[(size_t)r * N + ccol] = lo;
                    split2(x2, x3, hi, lo);
                    *(uint32_t*)&Ch[(size_t)(r + 8) * N + ccol] = hi;
                    *(uint32_t*)&Cl[(size_t)(r + 8) * N + ccol] = lo;
                }
            }
        }
    }
}

#define GEMM_SMEM128 (2 * (20480 + 2 * 128 * 80))
#define GEMM_SMEM64  (2 * (20480 + 2 * 64 * 80))

// ---------------- tensor-core causal flash attention (bf16x3, BM=64, R6) ----------------
#define FA_STRIDE 144
#define FA_QTILE  9216
#define FA_STAGE  (4 * FA_QTILE)
#define FA_SMEM   (2 * FA_QTILE + 2 * FA_STAGE)

__device__ __forceinline__ void fa_load_kv(uint32_t dst,
                                           const bf16* qh_, const bf16* ql_,
                                           size_t kbase, int tid) {
    #pragma unroll
    for (int i = 0; i < 16; i++) {
        const int t = i >> 2;
        int g = tid + (i & 3) * 128;
        int r = g >> 3, c = g & 7;
        const bf16* base = (t & 1) ? ql_ : qh_;
        const bf16* src = base + kbase + ((t >> 1) ? (size_t)DIM : (size_t)0)
                          + (size_t)r * TD + c * 8;
        CP_ASYNC16(dst + t * FA_QTILE + r * FA_STRIDE + c * 16, src);
    }
}

__global__ __launch_bounds__(128)
void flash_attn_tc(const bf16* __restrict__ qh_, const bf16* __restrict__ ql_,
                   bf16* __restrict__ oh_, bf16* __restrict__ ol_) {
    extern __shared__ char dsm[];
    uint32_t sb = smem_u32(dsm);
    const int qb = gridDim.x - 1 - blockIdx.x;
    const int bh = blockIdx.y;
    const int b = bh / NH, hh = bh % NH;
    const int tid = threadIdx.x, lane = tid & 31, w = tid >> 5;
    const int wrow = w * 16;

    {
        size_t qrow0 = ((size_t)(b * SEQ + qb * 64)) * TD + hh * HD;
        #pragma unroll
        for (int i = 0; i < 8; i++) {
            const int t = i >> 2;
            int g = tid + (i & 3) * 128;
            int r = g >> 3, c = g & 7;
            const bf16* src = (t ? ql_ : qh_) + qrow0 + (size_t)r * TD + c * 8;
            CP_ASYNC16(sb + t * FA_QTILE + r * FA_STRIDE + c * 16, src);
        }
    }
    fa_load_kv(sb + 2 * FA_QTILE, qh_, ql_,
               ((size_t)(b * SEQ)) * TD + DIM + hh * HD, tid);
    CP_COMMIT();

    const uint32_t lmA = sb + (uint32_t)((wrow + (lane & 7) + ((lane >> 3) & 1) * 8) * FA_STRIDE
                                         + ((lane >> 4) & 1) * 16);
    const uint32_t lmB = (uint32_t)((lane & 15) * FA_STRIDE + ((lane >> 4) & 1) * 16);
    const uint32_t lmV = lmB;

    float oacc[8][4] = {};
    float mi[2] = { -1e30f, -1e30f };
    float li[2] = { 0.0f, 0.0f };

    for (int kt = 0; kt <= qb; kt++) {
        CP_WAIT0();
        __syncthreads();
        if (kt < qb) {
            fa_load_kv(sb + 2 * FA_QTILE + ((kt + 1) & 1) * FA_STAGE, qh_, ql_,
                       ((size_t)(b * SEQ + (kt + 1) * 64)) * TD + DIM + hh * HD, tid);
            CP_COMMIT();
        }
        const uint32_t stg = sb + 2 * FA_QTILE + (uint32_t)((kt & 1) * FA_STAGE);
        const uint32_t sK = stg, sV = stg + 2 * FA_QTILE;

        float sacc[8][4] = {};
        #pragma unroll
        for (int ks = 0; ks < 4; ks++) {
            uint32_t qhf[4], qlf[4];
            LDSM4(qhf[0], qhf[1], qhf[2], qhf[3], lmA + ks * 32);
            LDSM4(qlf[0], qlf[1], qlf[2], qlf[3], lmA + FA_QTILE + ks * 32);
            #pragma unroll
            for (int jp = 0; jp < 4; jp++) {
                uint32_t r0, r1, r2, r3;
                uint32_t bh0[2], bh1[2], bl0[2], bl1[2];
                uint32_t kb = sK + (uint32_t)(jp * 16 * FA_STRIDE) + lmB + ks * 32;
                LDSM4(r0, r1, r2, r3, kb);
                bh0[0] = r0; bh0[1] = r2; bh1[0] = r1; bh1[1] = r3;
                LDSM4(r0, r1, r2, r3, kb + FA_QTILE);
                bl0[0] = r0; bl0[1] = r2; bl1[0] = r1; bl1[1] = r3;
                MMA16816(sacc[2 * jp],     qhf, bh0);
                MMA16816(sacc[2 * jp],     qhf, bl0);
                MMA16816(sacc[2 * jp],     qlf, bh0);
                MMA16816(sacc[2 * jp + 1], qhf, bh1);
                MMA16816(sacc[2 * jp + 1], qhf, bl1);
                MMA16816(sacc[2 * jp + 1], qlf, bh1);
            }
        }

        if (kt == qb) {
            #pragma unroll
            for (int nt = 0; nt < 8; nt++)
                #pragma unroll
                for (int e = 0; e < 4; e++) {
                    int jl = nt * 8 + (lane & 3) * 2 + (e & 1);
                    int il = wrow + (lane >> 2) + (e >> 1) * 8;
                    float s = sacc[nt][e];
                    sacc[nt][e] = (jl <= il) ? s * 0.125f : -1e4f;
                }
        } else {
            #pragma unroll
            for (int nt = 0; nt < 8; nt++)
                #pragma unroll
                for (int e = 0; e < 4; e++)
                    sacc[nt][e] *= 0.125f;
        }

        #pragma unroll
        for (int hf = 0; hf < 2; hf++) {
            const int e0 = hf * 2;
            float mx = -1e30f;
            #pragma unroll
            for (int nt = 0; nt < 8; nt++)
                mx = fmaxf(mx, fmaxf(sacc[nt][e0], sacc[nt][e0 + 1]));
            mx = fmaxf(mx, __shfl_xor_sync(0xffffffffu, mx, 1));
            mx = fmaxf(mx, __shfl_xor_sync(0xffffffffu, mx, 2));
            float mn = fmaxf(mi[hf], mx);
            float alpha = __expf(mi[hf] - mn);
            float sum = 0.0f;
            #pragma unroll
            for (int nt = 0; nt < 8; nt++) {
                float p0 = __expf(sacc[nt][e0] - mn);
                float p1 = __expf(sacc[nt][e0 + 1] - mn);
                sacc[nt][e0] = p0; sacc[nt][e0 + 1] = p1;
                sum += p0 + p1;
            }
            sum += __shfl_xor_sync(0xffffffffu, sum, 1);
            sum += __shfl_xor_sync(0xffffffffu, sum, 2);
            li[hf] = li[hf] * alpha + sum;
            mi[hf] = mn;
            #pragma unroll
            for (int nt = 0; nt < 8; nt++) {
                oacc[nt][e0]     *= alpha;
                oacc[nt][e0 + 1] *= alpha;
            }
        }

        #pragma unroll
        for (int kk = 0; kk < 4; kk++) {
            uint32_t ph[4], pl[4];
            split2(sacc[2 * kk][0],     sacc[2 * kk][1],     ph[0], pl[0]);
            split2(sacc[2 * kk][2],     sacc[2 * kk][3],     ph[1], pl[1]);
            split2(sacc[2 * kk + 1][0], sacc[2 * kk + 1][1], ph[2], pl[2]);
            split2(sacc[2 * kk + 1][2], sacc[2 * kk + 1][3], ph[3], pl[3]);
            #pragma unroll
            for (int dp = 0; dp < 4; dp++) {
                uint32_t h0, h1, h2, h3, l0, l1, l2, l3;
                uint32_t vb = sV + (uint32_t)(kk * 16 * FA_STRIDE + dp * 32) + lmV;
                LDSM4T(h0, h1, h2, h3, vb);
                LDSM4T(l0, l1, l2, l3, vb + FA_QTILE);
                uint32_t vh0[2] = { h0, h1 }, vh1[2] = { h2, h3 };
                uint32_t vl0[2] = { l0, l1 }, vl1[2] = { l2, l3 };
                MMA16816(oacc[2 * dp],     ph, vh0);
                MMA16816(oacc[2 * dp],     ph, vl0);
                MMA16816(oacc[2 * dp],     pl, vh0);
                MMA16816(oacc[2 * dp + 1], ph, vh1);
                MMA16816(oacc[2 * dp + 1], ph, vl1);
                MMA16816(oacc[2 * dp + 1], pl, vh1);
            }
        }
    }

    const float inv0 = 1.0f / li[0], inv1 = 1.0f / li[1];
    const int i0 = qb * 64 + wrow + (lane >> 2);
    const size_t row0 = ((size_t)(b * SEQ) + i0) * DIM + hh * HD;
    const size_t row1 = row0 + (size_t)8 * DIM;
    #pragma unroll
    for (int nt = 0; nt < 8; nt++) {
        int d = nt * 8 + (lane & 3) * 2;
        uint32_t hi, lo;
        split2(oacc[nt][0] * inv0, oacc[nt][1] * inv0, hi, lo);
        *(uint32_t*)&oh_[row0 + d] = hi;
        *(uint32_t*)&ol_[row0 + d] = lo;
        split2(oacc[nt][2] * inv1, oacc[nt][3] * inv1, hi, lo);
        *(uint32_t*)&oh_[row1 + d] = hi;
        *(uint32_t*)&ol_[row1 + d] = lo;
    }
}

// ---------------- vectorized layernorm (+ optional split), 192 thr/row ----------------
__global__ __launch_bounds__(192)
void ln_only(const float* __restrict__ x,
             const float* __restrict__ w, const float* __restrict__ bvec,
             float* __restrict__ out,
             bf16* __restrict__ oh, bf16* __restrict__ ol) {
    int row = blockIdx.x;
    int tid = threadIdx.x;                  // 0..191, each owns 4 elems
    int c = tid * 4;
    float4 v = *(const float4*)&x[(size_t)row * DIM + c];
    float s = v.x + v.y + v.z + v.w;

    __shared__ float red[6];
    #pragma unroll
    for (int o = 16; o; o >>= 1) s += __shfl_xor_sync(0xffffffffu, s, o);
    if ((tid & 31) == 0) red[tid >> 5] = s;
    __syncthreads();
    float tot = 0.0f;
    #pragma unroll
    for (int i = 0; i < 6; i++) tot += red[i];
    float mu = tot * (1.0f / DIM);

    float dx = v.x - mu, dy = v.y - mu, dz = v.z - mu, dw = v.w - mu;
    float s2 = dx * dx + dy * dy + dz * dz + dw * dw;
    __syncthreads();   // red reuse
    #pragma unroll
    for (int o = 16; o; o >>= 1) s2 += __shfl_xor_sync(0xffffffffu, s2, o);
    if ((tid & 31) == 0) red[tid >> 5] = s2;
    __syncthreads();
    float tot2 = 0.0f;
    #pragma unroll
    for (int i = 0; i < 6; i++) tot2 += red[i];
    float rinv = rsqrtf(tot2 * (1.0f / DIM) + 1e-5f);

    float4 w4 = *(const float4*)&w[c];
    float4 b4 = *(const float4*)&bvec[c];
    float4 o4;
    o4.x = dx * rinv * w4.x + b4.x;
    o4.y = dy * rinv * w4.y + b4.y;
    o4.z = dz * rinv * w4.z + b4.z;
    o4.w = dw * rinv * w4.w + b4.w;
    size_t off = (size_t)row * DIM + c;
    *(float4*)&out[off] = o4;
    if (oh) {
        uint32_t h01, l01, h23, l23;
        split2(o4.x, o4.y, h01, l01);
        split2(o4.z, o4.w, h23, l23);
        *(uint2*)&oh[off] = make_uint2(h01, h23);
        *(uint2*)&ol[off] = make_uint2(l01, l23);
    }
}

// ---------------- launch ----------------
extern "C" void kernel_launch(void* const* d_in, const int* in_sizes, int n_in,
                              void* d_out, int out_size) {
    (void)in_sizes; (void)n_in; (void)out_size;
    const int*   ids      = (const int*)  d_in[0];
    const float* tok_emb  = (const float*)d_in[3];
    const float* pos_emb  = (const float*)d_in[4];
    const float* c_attn_w = (const float*)d_in[5];
    const float* c_attn_b = (const float*)d_in[6];
    const float* c_proj_w = (const float*)d_in[7];
    const float* c_proj_b = (const float*)d_in[8];
    const float* ln1_w    = (const float*)d_in[9];
    const float* ln1_b    = (const float*)d_in[10];
    const float* c_fc_w   = (const float*)d_in[11];
    const float* c_fc_b   = (const float*)d_in[12];
    const float* mlp_w    = (const float*)d_in[13];
    const float* mlp_b    = (const float*)d_in[14];
    const float* ln2_w    = (const float*)d_in[15];
    const float* ln2_b    = (const float*)d_in[16];
    float* out = (float*)d_out;

    float *h, *a, *n, *m;
    bf16 *hh, *hl, *qkvh, *qkvl, *ath, *atl, *nh, *nl, *fch, *fcl;
    bf16 *wqh, *wql, *wph, *wpl, *wfh, *wfl, *wmh, *wml;
    cudaGetSymbolAddress((void**)&h,    g_h);
    cudaGetSymbolAddress((void**)&a,    g_a);
    cudaGetSymbolAddress((void**)&n,    g_n);
    cudaGetSymbolAddress((void**)&m,    g_m);
    cudaGetSymbolAddress((void**)&hh,   g_hh);
    cudaGetSymbolAddress((void**)&hl,   g_hl);
    cudaGetSymbolAddress((void**)&qkvh, g_qkvh);
    cudaGetSymbolAddress((void**)&qkvl, g_qkvl);
    cudaGetSymbolAddress((void**)&ath,  g_ath);
    cudaGetSymbolAddress((void**)&atl,  g_atl);
    cudaGetSymbolAddress((void**)&nh,   g_nh);
    cudaGetSymbolAddress((void**)&nl,   g_nl);
    cudaGetSymbolAddress((void**)&fch,  g_fch);
    cudaGetSymbolAddress((void**)&fcl,  g_fcl);
    cudaGetSymbolAddress((void**)&wqh,  g_wqh);
    cudaGetSymbolAddress((void**)&wql,  g_wql);
    cudaGetSymbolAddress((void**)&wph,  g_wph);
    cudaGetSymbolAddress((void**)&wpl,  g_wpl);
    cudaGetSymbolAddress((void**)&wfh,  g_wfh);
    cudaGetSymbolAddress((void**)&wfl,  g_wfl);
    cudaGetSymbolAddress((void**)&wmh,  g_wmh);
    cudaGetSymbolAddress((void**)&wml,  g_wml);

    cudaFuncSetAttribute(gemm_p<1, 128>, cudaFuncAttributeMaxDynamicSharedMemorySize, GEMM_SMEM128);
    cudaFuncSetAttribute(gemm_p<2, 128>, cudaFuncAttributeMaxDynamicSharedMemorySize, GEMM_SMEM128);
    cudaFuncSetAttribute(gemm_p<0, 64>,  cudaFuncAttributeMaxDynamicSharedMemorySize, GEMM_SMEM64);
    cudaFuncSetAttribute(flash_attn_tc,  cudaFuncAttributeMaxDynamicSharedMemorySize, FA_SMEM);

    // all weight transposes up front (batched over layers)
    transpose_conv<<<dim3(TD / 32, DIM / 32, NLAYER), 256>>>(c_attn_w, wqh, wql, DIM, TD);
    transpose_conv<<<dim3(DIM / 32, DIM / 32, NLAYER), 256>>>(c_proj_w, wph, wpl, DIM, DIM);
    transpose_conv<<<dim3(FD / 32, DIM / 32, NLAYER), 256>>>(c_fc_w, wfh, wfl, DIM, FD);
    transpose_conv<<<dim3(DIM / 32, FD / 32, NLAYER), 256>>>(mlp_w, wmh, wml, FD, DIM);

    embed_kernel<<<MTOK * DIM / 4 / 256, 256>>>(ids, tok_emb, pos_emb, h, hh, hl);

    for (int l = 0; l < NLAYER; l++) {
        // qkv: [4096,768] @ [768,2304] -> split bf16 (576 tiles, packed grid)
        gemm_p<1, 128><<<576, 256, GEMM_SMEM128>>>(
            hh, hl, wqh + (size_t)l * TD * DIM, wql + (size_t)l * TD * DIM,
            c_attn_b + (size_t)l * TD, nullptr, nullptr, qkvh, qkvl, MTOK, TD, DIM);

        flash_attn_tc<<<dim3(SEQ / 64, BATCH * NH), 128, FA_SMEM>>>(qkvh, qkvl, ath, atl);

        // proj: [4096,768] @ [768,768] + residual h -> fp32 (384 tiles of 128x64)
        gemm_p<0, 64><<<384, 128, GEMM_SMEM64>>>(
            ath, atl, wph + (size_t)l * DIM * DIM, wpl + (size_t)l * DIM * DIM,
            c_proj_b + (size_t)l * DIM, h, a, nullptr, nullptr, MTOK, DIM, DIM);

        ln_only<<<MTOK, 192>>>(a, ln1_w + (size_t)l * DIM, ln1_b + (size_t)l * DIM,
                               n, nh, nl);

        // fc: [4096,768] @ [768,3072] + gelu -> split bf16 (768 tiles, packed grid)
        gemm_p<2, 128><<<768, 256, GEMM_SMEM128>>>(
            nh, nl, wfh + (size_t)l * FD * DIM, wfl + (size_t)l * FD * DIM,
            c_fc_b + (size_t)l * FD, nullptr, nullptr, fch, fcl, MTOK, FD, DIM);

        // mlp: [4096,3072] @ [3072,768] + residual n -> fp32 (384 tiles of 128x64)
        gemm_p<0, 64><<<384, 128, GEMM_SMEM64>>>(
            fch, fcl, wmh + (size_t)l * DIM * FD, wml + (size_t)l * DIM * FD,
            mlp_b + (size_t)l * DIM, n, m, nullptr, nullptr, MTOK, DIM, FD);

        bool last = (l == NLAYER - 1);
        ln_only<<<MTOK, 192>>>(m, ln2_w + (size_t)l * DIM, ln2_b + (size_t)l * DIM,
                               last ? out : h,
                               last ? nullptr : hh, last ? nullptr : hl);
    }
}